// round 13
// baseline (speedup 1.0000x reference)
#include <cuda_runtime.h>
#include <cuda_fp16.h>
#include <math.h>

#define Nn 50000
#define Hh 128
#define Ee 800000
#define NGg 64
#define EPSc 1e-5f
#define NB_SCAN 196   // ceil(50000/256)

// ---------------- device scratch (static globals; no allocation) ----------------
// All mutable state is zero at module load. Cleanup split to avoid races:
//  - d_gsum/d_gsq: zeroed by scatter_kernel (before any agg of the same run).
//  - d_deg/d_scan_state/d_ticket: zeroed by gemm_head epilogue (head never
//    reads them; next run's hist/scan are separate launches).
__device__ int    d_batch[Nn];
__device__ int    d_deg[Nn];
__device__ float  d_dis[Nn];
__device__ int    d_rowptr[Nn + 1];
__device__ int    d_cursor[Nn];
__device__ int2   d_colw[Ee];
__device__ unsigned long long d_scan_state[NB_SCAN];
__device__ unsigned d_ticket;
__device__ int    d_gstart[NGg + 1];
__device__ float  d_gcntf[NGg];
__device__ float  d_gsum[4 * NGg * Hh];
__device__ float  d_gsq[4 * NGg * Hh];
__device__ __half d_HAh[(size_t)Nn * Hh];   // fp16 hidden state A
__device__ __half d_HBh[(size_t)Nn * Hh];   // fp16 hidden state B
__device__ __half d_Th[(size_t)Nn * Hh];    // fp16 GEMM output (gather source)
__device__ __half d_Ah[(size_t)Nn * Hh];    // fp16 aggregated pre-norm
__device__ __half d_Wh[5 * Hh * Hh];        // fp16 weights: W1,Wm0,Wm1,WL,Wp1

__device__ __forceinline__ uint2 f4_to_h4(float4 v) {
    uint2 o;
    *(__half2*)&o.x = __floats2half2_rn(v.x, v.y);
    *(__half2*)&o.y = __floats2half2_rn(v.z, v.w);
    return o;
}
__device__ __forceinline__ float4 h4_to_f4(uint2 u) {
    float2 a = __half22float2(*(__half2*)&u.x);
    float2 b = __half22float2(*(__half2*)&u.y);
    return make_float4(a.x, a.y, b.x, b.y);
}

// ---------------- dtype detection (per-block, no global state) ----------------
__device__ __forceinline__ int detect_is64(const void* ei) {
    const long long* p = (const long long*)ei;
    int ok = 1;
#pragma unroll
    for (int k = 0; k < 16; k++) {
        long long v = p[k];
        if (v < 0 || v >= (long long)Nn) ok = 0;
    }
    return ok;
}

// ---------------- preprocessing ----------------

// weight fp16 conversion (stream 0; feeds gemm_l1)
__global__ void convert_w_kernel(const float* __restrict__ W1, const float* __restrict__ Wm,
                                 const float* __restrict__ WL, const float* __restrict__ Wp1) {
    int i = blockIdx.x * blockDim.x + threadIdx.x;  // over 5*4096 float4 groups
    if (i >= 5 * 4096) return;
    int m = i >> 12;
    int j = i & 4095;
    const float* src;
    switch (m) {
        case 0: src = W1; break;
        case 1: src = Wm; break;
        case 2: src = Wm + 16384; break;
        case 3: src = WL; break;
        default: src = Wp1; break;
    }
    ((uint2*)d_Wh)[i] = f4_to_h4(((const float4*)src)[j]);
}

// batch convert + dst-degree histogram, vectorized loads (stream 1)
__global__ void hist_kernel(const void* ei, const void* bt) {
    __shared__ int s_is64;
    if (threadIdx.x == 0) s_is64 = detect_is64(ei);
    __syncthreads();
    int gtid = blockIdx.x * blockDim.x + threadIdx.x;
    int stride = gridDim.x * blockDim.x;
    if (s_is64) {
        const longlong2* p = (const longlong2*)((const long long*)ei + Ee);
        for (int i = gtid; i < Ee / 2; i += stride) {
            longlong2 v = p[i];
            atomicAdd(&d_deg[(int)v.x], 1);
            atomicAdd(&d_deg[(int)v.y], 1);
        }
        const longlong2* pb = (const longlong2*)bt;
        for (int i = gtid; i < Nn / 2; i += stride) {
            longlong2 v = pb[i];
            d_batch[2 * i] = (int)v.x;
            d_batch[2 * i + 1] = (int)v.y;
        }
    } else {
        const int4* p = (const int4*)((const int*)ei + Ee);
        for (int i = gtid; i < Ee / 4; i += stride) {
            int4 v = p[i];
            atomicAdd(&d_deg[v.x], 1);
            atomicAdd(&d_deg[v.y], 1);
            atomicAdd(&d_deg[v.z], 1);
            atomicAdd(&d_deg[v.w], 1);
        }
        const int4* pb = (const int4*)bt;
        for (int i = gtid; i < Nn / 4; i += stride) {
            ((int4*)d_batch)[i] = pb[i];
        }
    }
}

// decoupled-lookback scan of d_deg -> rowptr/cursor/dis + per-graph ranges
__global__ void scan_fused_kernel() {
    __shared__ unsigned sbid;
    __shared__ int s_excl;
    __shared__ int sh[256];
    if (threadIdx.x == 0) sbid = atomicAdd(&d_ticket, 1u);
    __syncthreads();
    int b = (int)sbid;
    int idx = b * 256 + threadIdx.x;
    int deg = (idx < Nn) ? d_deg[idx] : 0;
    sh[threadIdx.x] = deg;
    __syncthreads();
    for (int off = 1; off < 256; off <<= 1) {
        int u = 0;
        if (threadIdx.x >= off) u = sh[threadIdx.x - off];
        __syncthreads();
        if (threadIdx.x >= off) sh[threadIdx.x] += u;
        __syncthreads();
    }
    int incl = sh[threadIdx.x];
    int aggr = sh[255];
    if (threadIdx.x == 0) {
        if (b == 0) {
            atomicExch(&d_scan_state[0], (2ull << 32) | (unsigned)aggr);
            s_excl = 0;
        } else {
            atomicExch(&d_scan_state[b], (1ull << 32) | (unsigned)aggr);
            int excl = 0;
            int j = b - 1;
            while (true) {
                unsigned long long st;
                do { st = atomicAdd(&d_scan_state[j], 0ull); } while ((st >> 32) == 0ull);
                excl += (int)(unsigned)st;
                if ((st >> 32) == 2ull) break;
                j--;
            }
            atomicExch(&d_scan_state[b], (2ull << 32) | (unsigned)(excl + aggr));
            s_excl = excl;
        }
    }
    __syncthreads();
    int excl = s_excl;
    if (idx < Nn) {
        d_rowptr[idx + 1] = excl + incl;
        if (idx == 0) d_rowptr[0] = 0;
        d_cursor[idx] = excl + incl - deg;
        d_dis[idx] = rsqrtf((float)deg + 1.0f);
    }
    if (b == 0) {
        int t = threadIdx.x;
        if (t <= NGg) {
            int lo = 0, hi = Nn;
            while (lo < hi) {
                int mid = (lo + hi) >> 1;
                if (d_batch[mid] < t) lo = mid + 1; else hi = mid;
            }
            d_gstart[t] = lo;
        }
        __syncthreads();
        if (t < NGg) {
            int c = d_gstart[t + 1] - d_gstart[t];
            d_gcntf[t] = (c > 0) ? (float)c : 1.0f;
        }
    }
}

// scatter edges into CSR + zero gsum/gsq accumulators for this run
__global__ void scatter_kernel(const void* ei) {
    __shared__ int s_is64;
    if (threadIdx.x == 0) s_is64 = detect_is64(ei);
    __syncthreads();
    int i = blockIdx.x * blockDim.x + threadIdx.x;
    if (i < 4 * NGg * Hh) { d_gsum[i] = 0.f; d_gsq[i] = 0.f; }
    if (i >= Ee) return;
    int s, dd;
    if (s_is64) {
        s  = (int)((const long long*)ei)[i];
        dd = (int)((const long long*)ei)[Ee + i];
    } else {
        s  = ((const int*)ei)[i];
        dd = ((const int*)ei)[Ee + i];
    }
    int pos = atomicAdd(&d_cursor[dd], 1);
    d_colw[pos] = make_int2(s, __float_as_int(d_dis[s] * d_dis[dd]));
}

// ---------------- fp16 tensor-core GEMM (ldmatrix + mma.m16n8k16) -------------
// Y[n,128] = X[n,128] @ W[128,128]; fp16 operands, fp32 accumulate.
// 256 threads = 8 warps: wy=warp&3 -> rows wy*16..+15 ; wx=warp>>2 -> cols wx*64..+63
#define XPITCH 136
#define WPITCH 136
#define TILE_M 64
#define GEMM_SMEM ((TILE_M * XPITCH + 128 * WPITCH) * 2)

__device__ __forceinline__ void ldm_x4(unsigned& r0, unsigned& r1, unsigned& r2,
                                       unsigned& r3, unsigned addr) {
    asm volatile("ldmatrix.sync.aligned.m8n8.x4.shared.b16 {%0,%1,%2,%3}, [%4];"
                 : "=r"(r0), "=r"(r1), "=r"(r2), "=r"(r3) : "r"(addr));
}
__device__ __forceinline__ void ldm_x4t(unsigned& r0, unsigned& r1, unsigned& r2,
                                        unsigned& r3, unsigned addr) {
    asm volatile("ldmatrix.sync.aligned.m8n8.x4.trans.shared.b16 {%0,%1,%2,%3}, [%4];"
                 : "=r"(r0), "=r"(r1), "=r"(r2), "=r"(r3) : "r"(addr));
}

// stage X tile: fp32 source (layer 1) — convert
__device__ __forceinline__ void stage_X(const float* __restrict__ X, __half* Xs,
                                        int row0, int n, int tid) {
#pragma unroll
    for (int i = 0; i < 8; i++) {
        int idx = i * 256 + tid;
        int r = idx >> 5;
        int c = (idx & 31) * 4;
        float4 xv = make_float4(0.f, 0.f, 0.f, 0.f);
        if (row0 + r < n) xv = *(const float4*)&X[(size_t)(row0 + r) * 128 + c];
        *(uint2*)&Xs[r * XPITCH + c] = f4_to_h4(xv);
    }
}
// stage X tile: fp16 source — straight copy (uint4 = 8 halves)
__device__ __forceinline__ void stage_X(const __half* __restrict__ X, __half* Xs,
                                        int row0, int n, int tid) {
#pragma unroll
    for (int i = 0; i < 4; i++) {
        int idx = i * 256 + tid;
        int r = idx >> 4;
        int c = (idx & 15) * 8;
        uint4 v = make_uint4(0u, 0u, 0u, 0u);
        if (row0 + r < n) v = *(const uint4*)&X[(size_t)(row0 + r) * 128 + c];
        *(uint4*)&Xs[r * XPITCH + c] = v;
    }
}
// stage W (always fp16): 128x128 halves, straight copy
__device__ __forceinline__ void stage_W(const __half* __restrict__ W, __half* Ws, int tid) {
#pragma unroll
    for (int i = 0; i < 8; i++) {
        int idx = i * 256 + tid;
        int r = idx >> 4;
        int c = (idx & 15) * 8;
        *(uint4*)&Ws[r * WPITCH + c] = *(const uint4*)&W[r * 128 + c];
    }
}

#define FP16_GEMM_CORE()                                                          \
    extern __shared__ __align__(16) char smem_raw[];                              \
    __half* Xs = (__half*)smem_raw;                                               \
    __half* Ws = Xs + TILE_M * XPITCH;                                            \
    const int tid = threadIdx.x;                                                  \
    const int row0 = blockIdx.x * TILE_M;                                         \
    stage_W(W, Ws, tid);                                                          \
    stage_X(X, Xs, row0, n, tid);                                                 \
    __syncthreads();                                                              \
    const int warp = tid >> 5;                                                    \
    const int lane = tid & 31;                                                    \
    const int qr = lane >> 2;                                                     \
    const int qc = lane & 3;                                                      \
    const int wy = warp & 3;                                                      \
    const int wx = warp >> 2;                                                     \
    const int m0 = wy * 16;                                                       \
    const int n0 = wx * 64;                                                       \
    const int trow = lane & 7;                                                    \
    const int tsel = lane >> 3;                                                   \
    unsigned xs_b = (unsigned)__cvta_generic_to_shared(Xs);                       \
    unsigned ws_b = (unsigned)__cvta_generic_to_shared(Ws);                       \
    unsigned a_addr = xs_b +                                                      \
        ((m0 + trow + 8 * (tsel & 1)) * XPITCH + 8 * (tsel >> 1)) * 2;            \
    unsigned b_addr = ws_b +                                                      \
        ((trow + 8 * (tsel & 1)) * WPITCH + n0 + 8 * (tsel >> 1)) * 2;            \
    float acc[8][4];                                                              \
    _Pragma("unroll")                                                             \
    for (int t = 0; t < 8; t++) {                                                 \
        acc[t][0] = 0.f; acc[t][1] = 0.f; acc[t][2] = 0.f; acc[t][3] = 0.f;       \
    }                                                                             \
    _Pragma("unroll")                                                             \
    for (int ks = 0; ks < 8; ks++) {                                              \
        unsigned a0, a1, a2, a3;                                                  \
        ldm_x4(a0, a1, a2, a3, a_addr + ks * 32);                                 \
        _Pragma("unroll")                                                         \
        for (int tp = 0; tp < 4; tp++) {                                          \
            unsigned b0, b1, b2, b3;                                              \
            ldm_x4t(b0, b1, b2, b3, b_addr + ks * (16 * WPITCH * 2) + tp * 32);   \
            asm volatile(                                                         \
                "mma.sync.aligned.m16n8k16.row.col.f32.f16.f16.f32 "              \
                "{%0,%1,%2,%3}, {%4,%5,%6,%7}, {%8,%9}, {%0,%1,%2,%3};"           \
                : "+f"(acc[2 * tp][0]), "+f"(acc[2 * tp][1]),                     \
                  "+f"(acc[2 * tp][2]), "+f"(acc[2 * tp][3])                      \
                : "r"(a0), "r"(a1), "r"(a2), "r"(a3), "r"(b0), "r"(b1));          \
            asm volatile(                                                         \
                "mma.sync.aligned.m16n8k16.row.col.f32.f16.f16.f32 "              \
                "{%0,%1,%2,%3}, {%4,%5,%6,%7}, {%8,%9}, {%0,%1,%2,%3};"           \
                : "+f"(acc[2 * tp + 1][0]), "+f"(acc[2 * tp + 1][1]),             \
                  "+f"(acc[2 * tp + 1][2]), "+f"(acc[2 * tp + 1][3])              \
                : "r"(a0), "r"(a1), "r"(a2), "r"(a3), "r"(b2), "r"(b3));          \
        }                                                                         \
    }                                                                             \
    const int r_lo = row0 + m0 + qr;                                              \
    const int r_hi = r_lo + 8;

// fp16-output GEMM (feeds edge gather); input fp32 or fp16
template <typename TIn>
__global__ __launch_bounds__(256) void gemm_fp16_half_kernel(
    const TIn* __restrict__ X, const __half* __restrict__ W,
    __half* __restrict__ Y, int n) {
    FP16_GEMM_CORE()
    if (r_lo < n) {
#pragma unroll
        for (int t = 0; t < 8; t++)
            *(__half2*)&Y[(size_t)r_lo * 128 + n0 + t * 8 + qc * 2] =
                __floats2half2_rn(acc[t][0], acc[t][1]);
    }
    if (r_hi < n) {
#pragma unroll
        for (int t = 0; t < 8; t++)
            *(__half2*)&Y[(size_t)r_hi * 128 + n0 + t * 8 + qc * 2] =
                __floats2half2_rn(acc[t][2], acc[t][3]);
    }
}

// final GEMM with fused predictor head + safe state cleanup (fp16 input).
__global__ __launch_bounds__(256) void gemm_fp16_head_kernel(
    const __half* __restrict__ X, const __half* __restrict__ W,
    const float* __restrict__ bp1, const float* __restrict__ Wp2,
    const float* __restrict__ bp2, float* __restrict__ out, int n) {
    FP16_GEMM_CORE()
    float p_lo = 0.f, p_hi = 0.f;
#pragma unroll
    for (int t = 0; t < 8; t++) {
        int c = n0 + t * 8 + qc * 2;
        float b0v = bp1[c], b1v = bp1[c + 1];
        float w0v = Wp2[c], w1v = Wp2[c + 1];
        p_lo += fmaxf(acc[t][0] + b0v, 0.f) * w0v + fmaxf(acc[t][1] + b1v, 0.f) * w1v;
        p_hi += fmaxf(acc[t][2] + b0v, 0.f) * w0v + fmaxf(acc[t][3] + b1v, 0.f) * w1v;
    }
    p_lo += __shfl_xor_sync(0xffffffffu, p_lo, 1);
    p_lo += __shfl_xor_sync(0xffffffffu, p_lo, 2);
    p_hi += __shfl_xor_sync(0xffffffffu, p_hi, 1);
    p_hi += __shfl_xor_sync(0xffffffffu, p_hi, 2);
    __syncthreads();
    float* s_head = (float*)smem_raw;  // 64 rows x 2 halves
    if (qc == 0) {
        s_head[(m0 + qr) * 2 + wx]     = p_lo;
        s_head[(m0 + qr + 8) * 2 + wx] = p_hi;
    }
    __syncthreads();
    if (tid < TILE_M) {
        int gr = row0 + tid;
        if (gr < n) {
            float z = s_head[tid * 2] + s_head[tid * 2 + 1] + bp2[0];
            out[gr] = 1.f / (1.f + expf(-z));
        }
    }
    // ---- safe cleanup (this kernel never reads these) ----
    int gt = blockIdx.x * 256 + tid;
    if (gt < Nn) d_deg[gt] = 0;
    if (gt < NB_SCAN) d_scan_state[gt] = 0ull;
    if (gt == 0) d_ticket = 0u;
}

// ---------------- CSR aggregation + fused per-graph sum/sumsq -----------------
// A stored fp16 (rounded at store); gsum/gsq accumulated from fp32 values.
__global__ void agg_kernel(const __half* __restrict__ T, const float* __restrict__ bias,
                           __half* __restrict__ A,
                           float* __restrict__ gsum, float* __restrict__ gsq) {
    __shared__ __align__(16) float s_red[2][8][132];
    __shared__ int s_same, s_g;
    int tid = threadIdx.x;
    int wid = tid >> 5;
    int lane = tid & 31;
    int node = blockIdx.x * 8 + wid;
    if (tid == 0) {
        int g0 = d_batch[blockIdx.x * 8];
        int g7 = d_batch[blockIdx.x * 8 + 7];
        s_same = (g0 == g7);
        s_g = g0;
    }
    int s = d_rowptr[node], e = d_rowptr[node + 1];
    float ax = 0.f, ay = 0.f, az = 0.f, aw = 0.f;
    int p = s;
    for (; p + 4 <= e; p += 4) {
        int2 e0 = d_colw[p], e1 = d_colw[p + 1], e2 = d_colw[p + 2], e3 = d_colw[p + 3];
        float w0 = __int_as_float(e0.y), w1 = __int_as_float(e1.y);
        float w2 = __int_as_float(e2.y), w3 = __int_as_float(e3.y);
        uint2 u0 = ((const uint2*)(T + (size_t)e0.x * 128))[lane];
        uint2 u1 = ((const uint2*)(T + (size_t)e1.x * 128))[lane];
        uint2 u2 = ((const uint2*)(T + (size_t)e2.x * 128))[lane];
        uint2 u3 = ((const uint2*)(T + (size_t)e3.x * 128))[lane];
        float2 a0 = __half22float2(*(__half2*)&u0.x), b0 = __half22float2(*(__half2*)&u0.y);
        float2 a1 = __half22float2(*(__half2*)&u1.x), b1 = __half22float2(*(__half2*)&u1.y);
        float2 a2 = __half22float2(*(__half2*)&u2.x), b2 = __half22float2(*(__half2*)&u2.y);
        float2 a3 = __half22float2(*(__half2*)&u3.x), b3 = __half22float2(*(__half2*)&u3.y);
        ax += w0 * a0.x + w1 * a1.x + w2 * a2.x + w3 * a3.x;
        ay += w0 * a0.y + w1 * a1.y + w2 * a2.y + w3 * a3.y;
        az += w0 * b0.x + w1 * b1.x + w2 * b2.x + w3 * b3.x;
        aw += w0 * b0.y + w1 * b1.y + w2 * b2.y + w3 * b3.y;
    }
    for (; p < e; p++) {
        int2 ec = d_colw[p];
        float w = __int_as_float(ec.y);
        uint2 u = ((const uint2*)(T + (size_t)ec.x * 128))[lane];
        float2 a = __half22float2(*(__half2*)&u.x), b = __half22float2(*(__half2*)&u.y);
        ax += w * a.x; ay += w * a.y; az += w * b.x; aw += w * b.y;
    }
    float ds = d_dis[node];
    float sl = ds * ds;
    uint2 ut = ((const uint2*)(T + (size_t)node * 128))[lane];
    float2 ta = __half22float2(*(__half2*)&ut.x), tb = __half22float2(*(__half2*)&ut.y);
    float4 bb = *(const float4*)&bias[lane * 4];
    float4 o;
    o.x = ax + sl * ta.x + bb.x;
    o.y = ay + sl * ta.y + bb.y;
    o.z = az + sl * tb.x + bb.z;
    o.w = aw + sl * tb.y + bb.w;
    ((uint2*)(A + (size_t)node * 128))[lane] = f4_to_h4(o);

    *(float4*)&s_red[0][wid][lane * 4] = o;
    float4 o2 = make_float4(o.x * o.x, o.y * o.y, o.z * o.z, o.w * o.w);
    *(float4*)&s_red[1][wid][lane * 4] = o2;
    __syncthreads();
    if (s_same) {
        if (tid < 128) {
            float t1 = 0.f, t2 = 0.f;
#pragma unroll
            for (int k = 0; k < 8; k++) { t1 += s_red[0][k][tid]; t2 += s_red[1][k][tid]; }
            atomicAdd(&gsum[s_g * 128 + tid], t1);
            atomicAdd(&gsq[s_g * 128 + tid], t2);
        }
    } else {
        int g = d_batch[node];
        atomicAdd(&gsum[g * 128 + lane * 4 + 0], o.x);
        atomicAdd(&gsum[g * 128 + lane * 4 + 1], o.y);
        atomicAdd(&gsum[g * 128 + lane * 4 + 2], o.z);
        atomicAdd(&gsum[g * 128 + lane * 4 + 3], o.w);
        atomicAdd(&gsq[g * 128 + lane * 4 + 0], o2.x);
        atomicAdd(&gsq[g * 128 + lane * 4 + 1], o2.y);
        atomicAdd(&gsq[g * 128 + lane * 4 + 2], o2.z);
        atomicAdd(&gsq[g * 128 + lane * 4 + 3], o2.w);
    }
}

// out(fp16) = [in(fp16) +] relu((A(fp16) - alpha*mean)*rsqrt(var+eps)*gamma + beta)
template <int RES>
__global__ void final_kernel(const __half* __restrict__ A, const __half* __restrict__ in,
                             const float* __restrict__ alpha, const float* __restrict__ gamma,
                             const float* __restrict__ beta, __half* __restrict__ out,
                             const float* __restrict__ gsum, const float* __restrict__ gsq) {
    int idx = blockIdx.x * blockDim.x + threadIdx.x;  // over N*32 groups of 4
    if (idx >= Nn * 32) return;
    int node = idx >> 5;
    int q = idx & 31;
    int g = d_batch[node];
    float inv = 1.f / d_gcntf[g];
    float4 a  = h4_to_f4(((const uint2*)A)[idx]);
    float4 gs = *(const float4*)&gsum[g * 128 + q * 4];
    float4 gq = *(const float4*)&gsq[g * 128 + q * 4];
    float4 al = *(const float4*)&alpha[q * 4];
    float4 ga = *(const float4*)&gamma[q * 4];
    float4 be = *(const float4*)&beta[q * 4];
    float4 m, vv, o;
    m.x = gs.x * inv; m.y = gs.y * inv; m.z = gs.z * inv; m.w = gs.w * inv;
    vv.x = gq.x * inv - m.x * m.x * al.x * (2.f - al.x);
    vv.y = gq.y * inv - m.y * m.y * al.y * (2.f - al.y);
    vv.z = gq.z * inv - m.z * m.z * al.z * (2.f - al.z);
    vv.w = gq.w * inv - m.w * m.w * al.w * (2.f - al.w);
    o.x = fmaxf((a.x - al.x * m.x) * rsqrtf(vv.x + EPSc) * ga.x + be.x, 0.f);
    o.y = fmaxf((a.y - al.y * m.y) * rsqrtf(vv.y + EPSc) * ga.y + be.y, 0.f);
    o.z = fmaxf((a.z - al.z * m.z) * rsqrtf(vv.z + EPSc) * ga.z + be.z, 0.f);
    o.w = fmaxf((a.w - al.w * m.w) * rsqrtf(vv.w + EPSc) * ga.w + be.w, 0.f);
    if (RES) {
        uint2 r = ((const uint2*)in)[idx];
        float2 r0 = __half22float2(*(__half2*)&r.x);
        float2 r1 = __half22float2(*(__half2*)&r.y);
        o.x += r0.x; o.y += r0.y; o.z += r1.x; o.w += r1.y;
    }
    ((uint2*)out)[idx] = f4_to_h4(o);
}

// ---------------- host orchestration ----------------
extern "C" void kernel_launch(void* const* d_in, const int* in_sizes, int n_in,
                              void* d_out, int out_size) {
    const float* x   = (const float*)d_in[0];
    const void*  ei  = d_in[1];
    const void*  bt  = d_in[2];
    const float* W1  = (const float*)d_in[3];
    const float* b1  = (const float*)d_in[4];
    const float* a1  = (const float*)d_in[5];
    const float* g1  = (const float*)d_in[6];
    const float* be1 = (const float*)d_in[7];
    const float* Wm  = (const float*)d_in[8];
    const float* bm  = (const float*)d_in[9];
    const float* am  = (const float*)d_in[10];
    const float* gm  = (const float*)d_in[11];
    const float* bem = (const float*)d_in[12];
    const float* WL  = (const float*)d_in[13];
    const float* bL  = (const float*)d_in[14];
    const float* aL  = (const float*)d_in[15];
    const float* gL  = (const float*)d_in[16];
    const float* beL = (const float*)d_in[17];
    const float* Wp1 = (const float*)d_in[18];
    const float* bp1 = (const float*)d_in[19];
    const float* Wp2 = (const float*)d_in[20];
    const float* bp2 = (const float*)d_in[21];
    float* out = (float*)d_out;

    float *GS, *GQ;
    __half *HAh, *HBh, *Th, *Ah, *Wh;
    cudaGetSymbolAddress((void**)&HAh, d_HAh);
    cudaGetSymbolAddress((void**)&HBh, d_HBh);
    cudaGetSymbolAddress((void**)&Th,  d_Th);
    cudaGetSymbolAddress((void**)&Ah,  d_Ah);
    cudaGetSymbolAddress((void**)&GS,  d_gsum);
    cudaGetSymbolAddress((void**)&GQ,  d_gsq);
    cudaGetSymbolAddress((void**)&Wh,  d_Wh);

    // side stream + fork/join events (created once, on the correctness call;
    // streams/events are not device-memory allocations)
    static cudaStream_t s1 = nullptr;
    static cudaEvent_t evF = nullptr, evJ = nullptr;
    if (s1 == nullptr) {
        cudaStreamCreateWithFlags(&s1, cudaStreamNonBlocking);
        cudaEventCreateWithFlags(&evF, cudaEventDisableTiming);
        cudaEventCreateWithFlags(&evJ, cudaEventDisableTiming);
    }

    const int smem = GEMM_SMEM;
    cudaFuncSetAttribute(gemm_fp16_half_kernel<float>,  cudaFuncAttributeMaxDynamicSharedMemorySize, smem);
    cudaFuncSetAttribute(gemm_fp16_half_kernel<__half>, cudaFuncAttributeMaxDynamicSharedMemorySize, smem);
    cudaFuncSetAttribute(gemm_fp16_head_kernel, cudaFuncAttributeMaxDynamicSharedMemorySize, smem);

    const int gemm_grid = (Nn + TILE_M - 1) / TILE_M;  // 782
    const int agg_grid  = Nn / 8;   // 6250, exact
    const int elem_grid = (Nn * 32 + 511) / 512;
    const int GL = NGg * Hh;
    const int WSZ = Hh * Hh;

    // ---- fork: preprocessing chain on s1, weight-convert + layer-1 GEMM on s0 ----
    cudaEventRecord(evF, 0);
    cudaStreamWaitEvent(s1, evF, 0);

    // s1: CSR construction (independent of GEMM path)
    hist_kernel<<<1024, 256, 0, s1>>>(ei, bt);
    scan_fused_kernel<<<NB_SCAN, 256, 0, s1>>>();
    scatter_kernel<<<(Ee + 255) / 256, 256, 0, s1>>>(ei);  // also zeroes gsum/gsq
    cudaEventRecord(evJ, s1);

    // s0 (default): weights -> fp16, then layer-1 GEMM (needs only x and Wh)
    convert_w_kernel<<<80, 256>>>(W1, Wm, WL, Wp1);
    gemm_fp16_half_kernel<float><<<gemm_grid, 256, smem>>>(x, Wh + 0 * WSZ, Th, Nn);

    // join before the first aggregation
    cudaStreamWaitEvent(0, evJ, 0);

    // ---- layer 1 aggregate + norm -> HBh ----
    agg_kernel<<<agg_grid, 256>>>(Th, b1, Ah, GS + 0 * GL, GQ + 0 * GL);
    final_kernel<0><<<elem_grid, 512>>>(Ah, nullptr, a1, g1, be1, HBh, GS + 0 * GL, GQ + 0 * GL);

    // ---- mid layer 0 (residual): HBh -> HAh ----
    gemm_fp16_half_kernel<__half><<<gemm_grid, 256, smem>>>(HBh, Wh + 1 * WSZ, Th, Nn);
    agg_kernel<<<agg_grid, 256>>>(Th, bm + 0 * 128, Ah, GS + 1 * GL, GQ + 1 * GL);
    final_kernel<1><<<elem_grid, 512>>>(Ah, HBh, am + 0 * 128, gm + 0 * 128, bem + 0 * 128, HAh,
                                        GS + 1 * GL, GQ + 1 * GL);

    // ---- mid layer 1 (residual): HAh -> HBh ----
    gemm_fp16_half_kernel<__half><<<gemm_grid, 256, smem>>>(HAh, Wh + 2 * WSZ, Th, Nn);
    agg_kernel<<<agg_grid, 256>>>(Th, bm + 1 * 128, Ah, GS + 2 * GL, GQ + 2 * GL);
    final_kernel<1><<<elem_grid, 512>>>(Ah, HAh, am + 1 * 128, gm + 1 * 128, bem + 1 * 128, HBh,
                                        GS + 2 * GL, GQ + 2 * GL);

    // ---- last layer: HBh -> HAh ----
    gemm_fp16_half_kernel<__half><<<gemm_grid, 256, smem>>>(HBh, Wh + 3 * WSZ, Th, Nn);
    agg_kernel<<<agg_grid, 256>>>(Th, bL, Ah, GS + 3 * GL, GQ + 3 * GL);
    final_kernel<0><<<elem_grid, 512>>>(Ah, nullptr, aL, gL, beL, HAh, GS + 3 * GL, GQ + 3 * GL);

    // ---- predictor: HAh -> out (GEMM + fused head + safe cleanup) ----
    gemm_fp16_head_kernel<<<gemm_grid, 256, smem>>>(HAh, Wh + 4 * WSZ, bp1, Wp2, bp2, out, Nn);
}

// round 14
// speedup vs baseline: 1.0425x; 1.0425x over previous
#include <cuda_runtime.h>
#include <cuda_fp16.h>
#include <math.h>

#define Nn 50000
#define Hh 128
#define Ee 800000
#define NGg 64
#define EPSc 1e-5f
#define NB_SCAN 196   // ceil(50000/256)

// ---------------- device scratch (static globals; no allocation) ----------------
// All mutable state is zero at module load. Cleanup split to avoid races:
//  - d_gsum/d_gsq: zeroed by scatter_kernel (before any agg of the same run).
//  - d_deg/d_scan_state/d_ticket: zeroed by gemm_head epilogue (head never
//    reads them; next run's hist/scan are separate launches).
__device__ int    d_batch[Nn];
__device__ int    d_deg[Nn];
__device__ float  d_dis[Nn];
__device__ int    d_rowptr[Nn + 1];
__device__ int    d_cursor[Nn];
__device__ int2   d_colw[Ee];
__device__ unsigned long long d_scan_state[NB_SCAN];
__device__ unsigned d_ticket;
__device__ int    d_gstart[NGg + 1];
__device__ float  d_gcntf[NGg];
__device__ float  d_gsum[4 * NGg * Hh];
__device__ float  d_gsq[4 * NGg * Hh];
__device__ __half d_HAh[(size_t)Nn * Hh];   // fp16 hidden state A
__device__ __half d_HBh[(size_t)Nn * Hh];   // fp16 hidden state B
__device__ __half d_Th[(size_t)Nn * Hh];    // fp16 GEMM output (gather source)
__device__ float  d_A[(size_t)Nn * Hh];     // fp32 aggregated pre-norm
__device__ __half d_Wh[5 * Hh * Hh];        // fp16 weights: W1,Wm0,Wm1,WL,Wp1

__device__ __forceinline__ uint2 f4_to_h4(float4 v) {
    uint2 o;
    *(__half2*)&o.x = __floats2half2_rn(v.x, v.y);
    *(__half2*)&o.y = __floats2half2_rn(v.z, v.w);
    return o;
}

// ---------------- dtype detection (per-block, no global state) ----------------
__device__ __forceinline__ int detect_is64(const void* ei) {
    const long long* p = (const long long*)ei;
    int ok = 1;
#pragma unroll
    for (int k = 0; k < 16; k++) {
        long long v = p[k];
        if (v < 0 || v >= (long long)Nn) ok = 0;
    }
    return ok;
}

// ---------------- preprocessing ----------------

// convert ONLY W1 to fp16 (critical path before gemm_l1): 16 blocks
__global__ void convert_w1_kernel(const float* __restrict__ W1) {
    int i = blockIdx.x * blockDim.x + threadIdx.x;  // over 4096 float4 groups
    if (i >= 4096) return;
    ((uint2*)d_Wh)[i] = f4_to_h4(((const float4*)W1)[i]);
}

// convert the remaining 4 weight matrices (off the critical path)
__global__ void convert_wrest_kernel(const float* __restrict__ Wm,
                                     const float* __restrict__ WL,
                                     const float* __restrict__ Wp1) {
    int i = blockIdx.x * blockDim.x + threadIdx.x;  // over 4*4096 float4 groups
    if (i >= 4 * 4096) return;
    int m = i >> 12;
    int j = i & 4095;
    const float* src;
    switch (m) {
        case 0: src = Wm; break;
        case 1: src = Wm + 16384; break;
        case 2: src = WL; break;
        default: src = Wp1; break;
    }
    ((uint2*)d_Wh)[4096 + i] = f4_to_h4(((const float4*)src)[j]);
}

// batch convert + dst-degree histogram (stream 1)
__global__ void hist_kernel(const void* ei, const void* bt) {
    __shared__ int s_is64;
    if (threadIdx.x == 0) s_is64 = detect_is64(ei);
    __syncthreads();
    int is64 = s_is64;
    int gtid = blockIdx.x * blockDim.x + threadIdx.x;
    int stride = gridDim.x * blockDim.x;
    for (int i = gtid; i < Ee; i += stride) {
        int v = is64 ? (int)((const long long*)ei)[Ee + i] : ((const int*)ei)[Ee + i];
        atomicAdd(&d_deg[v], 1);
    }
    for (int i = gtid; i < Nn; i += stride) {
        int v = is64 ? (int)((const long long*)bt)[i] : ((const int*)bt)[i];
        d_batch[i] = v;
    }
}

// decoupled-lookback scan of d_deg -> rowptr/cursor/dis + per-graph ranges
__global__ void scan_fused_kernel() {
    __shared__ unsigned sbid;
    __shared__ int s_excl;
    __shared__ int sh[256];
    if (threadIdx.x == 0) sbid = atomicAdd(&d_ticket, 1u);
    __syncthreads();
    int b = (int)sbid;
    int idx = b * 256 + threadIdx.x;
    int deg = (idx < Nn) ? d_deg[idx] : 0;
    sh[threadIdx.x] = deg;
    __syncthreads();
    for (int off = 1; off < 256; off <<= 1) {
        int u = 0;
        if (threadIdx.x >= off) u = sh[threadIdx.x - off];
        __syncthreads();
        if (threadIdx.x >= off) sh[threadIdx.x] += u;
        __syncthreads();
    }
    int incl = sh[threadIdx.x];
    int aggr = sh[255];
    if (threadIdx.x == 0) {
        if (b == 0) {
            atomicExch(&d_scan_state[0], (2ull << 32) | (unsigned)aggr);
            s_excl = 0;
        } else {
            atomicExch(&d_scan_state[b], (1ull << 32) | (unsigned)aggr);
            int excl = 0;
            int j = b - 1;
            while (true) {
                unsigned long long st;
                do { st = atomicAdd(&d_scan_state[j], 0ull); } while ((st >> 32) == 0ull);
                excl += (int)(unsigned)st;
                if ((st >> 32) == 2ull) break;
                j--;
            }
            atomicExch(&d_scan_state[b], (2ull << 32) | (unsigned)(excl + aggr));
            s_excl = excl;
        }
    }
    __syncthreads();
    int excl = s_excl;
    if (idx < Nn) {
        d_rowptr[idx + 1] = excl + incl;
        if (idx == 0) d_rowptr[0] = 0;
        d_cursor[idx] = excl + incl - deg;
        d_dis[idx] = rsqrtf((float)deg + 1.0f);
    }
    if (b == 0) {
        int t = threadIdx.x;
        if (t <= NGg) {
            int lo = 0, hi = Nn;
            while (lo < hi) {
                int mid = (lo + hi) >> 1;
                if (d_batch[mid] < t) lo = mid + 1; else hi = mid;
            }
            d_gstart[t] = lo;
        }
        __syncthreads();
        if (t < NGg) {
            int c = d_gstart[t + 1] - d_gstart[t];
            d_gcntf[t] = (c > 0) ? (float)c : 1.0f;
        }
    }
}

// scatter edges into CSR + zero gsum/gsq accumulators for this run
__global__ void scatter_kernel(const void* ei) {
    __shared__ int s_is64;
    if (threadIdx.x == 0) s_is64 = detect_is64(ei);
    __syncthreads();
    int i = blockIdx.x * blockDim.x + threadIdx.x;
    if (i < 4 * NGg * Hh) { d_gsum[i] = 0.f; d_gsq[i] = 0.f; }
    if (i >= Ee) return;
    int s, dd;
    if (s_is64) {
        s  = (int)((const long long*)ei)[i];
        dd = (int)((const long long*)ei)[Ee + i];
    } else {
        s  = ((const int*)ei)[i];
        dd = ((const int*)ei)[Ee + i];
    }
    int pos = atomicAdd(&d_cursor[dd], 1);
    d_colw[pos] = make_int2(s, __float_as_int(d_dis[s] * d_dis[dd]));
}

// ---------------- fp16 tensor-core GEMM (ldmatrix + mma.m16n8k16) -------------
// Y[n,128] = X[n,128] @ W[128,128]; fp16 operands, fp32 accumulate.
// 256 threads = 8 warps: wy=warp&3 -> rows wy*16..+15 ; wx=warp>>2 -> cols wx*64..+63
#define XPITCH 136
#define WPITCH 136
#define TILE_M 64
#define GEMM_SMEM ((TILE_M * XPITCH + 128 * WPITCH) * 2)

__device__ __forceinline__ void ldm_x4(unsigned& r0, unsigned& r1, unsigned& r2,
                                       unsigned& r3, unsigned addr) {
    asm volatile("ldmatrix.sync.aligned.m8n8.x4.shared.b16 {%0,%1,%2,%3}, [%4];"
                 : "=r"(r0), "=r"(r1), "=r"(r2), "=r"(r3) : "r"(addr));
}
__device__ __forceinline__ void ldm_x4t(unsigned& r0, unsigned& r1, unsigned& r2,
                                        unsigned& r3, unsigned addr) {
    asm volatile("ldmatrix.sync.aligned.m8n8.x4.trans.shared.b16 {%0,%1,%2,%3}, [%4];"
                 : "=r"(r0), "=r"(r1), "=r"(r2), "=r"(r3) : "r"(addr));
}

// stage X tile: fp32 source (layer 1) — convert
__device__ __forceinline__ void stage_X(const float* __restrict__ X, __half* Xs,
                                        int row0, int n, int tid) {
#pragma unroll
    for (int i = 0; i < 8; i++) {
        int idx = i * 256 + tid;
        int r = idx >> 5;
        int c = (idx & 31) * 4;
        float4 xv = make_float4(0.f, 0.f, 0.f, 0.f);
        if (row0 + r < n) xv = *(const float4*)&X[(size_t)(row0 + r) * 128 + c];
        *(uint2*)&Xs[r * XPITCH + c] = f4_to_h4(xv);
    }
}
// stage X tile: fp16 source — straight copy (uint4 = 8 halves)
__device__ __forceinline__ void stage_X(const __half* __restrict__ X, __half* Xs,
                                        int row0, int n, int tid) {
#pragma unroll
    for (int i = 0; i < 4; i++) {
        int idx = i * 256 + tid;
        int r = idx >> 4;
        int c = (idx & 15) * 8;
        uint4 v = make_uint4(0u, 0u, 0u, 0u);
        if (row0 + r < n) v = *(const uint4*)&X[(size_t)(row0 + r) * 128 + c];
        *(uint4*)&Xs[r * XPITCH + c] = v;
    }
}
// stage W (always fp16): 128x128 halves, straight copy
__device__ __forceinline__ void stage_W(const __half* __restrict__ W, __half* Ws, int tid) {
#pragma unroll
    for (int i = 0; i < 8; i++) {
        int idx = i * 256 + tid;
        int r = idx >> 4;
        int c = (idx & 15) * 8;
        *(uint4*)&Ws[r * WPITCH + c] = *(const uint4*)&W[r * 128 + c];
    }
}

#define FP16_GEMM_CORE()                                                          \
    extern __shared__ __align__(16) char smem_raw[];                              \
    __half* Xs = (__half*)smem_raw;                                               \
    __half* Ws = Xs + TILE_M * XPITCH;                                            \
    const int tid = threadIdx.x;                                                  \
    const int row0 = blockIdx.x * TILE_M;                                         \
    stage_W(W, Ws, tid);                                                          \
    stage_X(X, Xs, row0, n, tid);                                                 \
    __syncthreads();                                                              \
    const int warp = tid >> 5;                                                    \
    const int lane = tid & 31;                                                    \
    const int qr = lane >> 2;                                                     \
    const int qc = lane & 3;                                                      \
    const int wy = warp & 3;                                                      \
    const int wx = warp >> 2;                                                     \
    const int m0 = wy * 16;                                                       \
    const int n0 = wx * 64;                                                       \
    const int trow = lane & 7;                                                    \
    const int tsel = lane >> 3;                                                   \
    unsigned xs_b = (unsigned)__cvta_generic_to_shared(Xs);                       \
    unsigned ws_b = (unsigned)__cvta_generic_to_shared(Ws);                       \
    unsigned a_addr = xs_b +                                                      \
        ((m0 + trow + 8 * (tsel & 1)) * XPITCH + 8 * (tsel >> 1)) * 2;            \
    unsigned b_addr = ws_b +                                                      \
        ((trow + 8 * (tsel & 1)) * WPITCH + n0 + 8 * (tsel >> 1)) * 2;            \
    float acc[8][4];                                                              \
    _Pragma("unroll")                                                             \
    for (int t = 0; t < 8; t++) {                                                 \
        acc[t][0] = 0.f; acc[t][1] = 0.f; acc[t][2] = 0.f; acc[t][3] = 0.f;       \
    }                                                                             \
    _Pragma("unroll")                                                             \
    for (int ks = 0; ks < 8; ks++) {                                              \
        unsigned a0, a1, a2, a3;                                                  \
        ldm_x4(a0, a1, a2, a3, a_addr + ks * 32);                                 \
        _Pragma("unroll")                                                         \
        for (int tp = 0; tp < 4; tp++) {                                          \
            unsigned b0, b1, b2, b3;                                              \
            ldm_x4t(b0, b1, b2, b3, b_addr + ks * (16 * WPITCH * 2) + tp * 32);   \
            asm volatile(                                                         \
                "mma.sync.aligned.m16n8k16.row.col.f32.f16.f16.f32 "              \
                "{%0,%1,%2,%3}, {%4,%5,%6,%7}, {%8,%9}, {%0,%1,%2,%3};"           \
                : "+f"(acc[2 * tp][0]), "+f"(acc[2 * tp][1]),                     \
                  "+f"(acc[2 * tp][2]), "+f"(acc[2 * tp][3])                      \
                : "r"(a0), "r"(a1), "r"(a2), "r"(a3), "r"(b0), "r"(b1));          \
            asm volatile(                                                         \
                "mma.sync.aligned.m16n8k16.row.col.f32.f16.f16.f32 "              \
                "{%0,%1,%2,%3}, {%4,%5,%6,%7}, {%8,%9}, {%0,%1,%2,%3};"           \
                : "+f"(acc[2 * tp + 1][0]), "+f"(acc[2 * tp + 1][1]),             \
                  "+f"(acc[2 * tp + 1][2]), "+f"(acc[2 * tp + 1][3])              \
                : "r"(a0), "r"(a1), "r"(a2), "r"(a3), "r"(b2), "r"(b3));          \
        }                                                                         \
    }                                                                             \
    const int r_lo = row0 + m0 + qr;                                              \
    const int r_hi = r_lo + 8;

// fp16-output GEMM (feeds edge gather); input fp32 or fp16
template <typename TIn>
__global__ __launch_bounds__(256) void gemm_fp16_half_kernel(
    const TIn* __restrict__ X, const __half* __restrict__ W,
    __half* __restrict__ Y, int n) {
    FP16_GEMM_CORE()
    if (r_lo < n) {
#pragma unroll
        for (int t = 0; t < 8; t++)
            *(__half2*)&Y[(size_t)r_lo * 128 + n0 + t * 8 + qc * 2] =
                __floats2half2_rn(acc[t][0], acc[t][1]);
    }
    if (r_hi < n) {
#pragma unroll
        for (int t = 0; t < 8; t++)
            *(__half2*)&Y[(size_t)r_hi * 128 + n0 + t * 8 + qc * 2] =
                __floats2half2_rn(acc[t][2], acc[t][3]);
    }
}

// final GEMM with fused predictor head + safe state cleanup (fp16 input).
__global__ __launch_bounds__(256) void gemm_fp16_head_kernel(
    const __half* __restrict__ X, const __half* __restrict__ W,
    const float* __restrict__ bp1, const float* __restrict__ Wp2,
    const float* __restrict__ bp2, float* __restrict__ out, int n) {
    FP16_GEMM_CORE()
    float p_lo = 0.f, p_hi = 0.f;
#pragma unroll
    for (int t = 0; t < 8; t++) {
        int c = n0 + t * 8 + qc * 2;
        float b0v = bp1[c], b1v = bp1[c + 1];
        float w0v = Wp2[c], w1v = Wp2[c + 1];
        p_lo += fmaxf(acc[t][0] + b0v, 0.f) * w0v + fmaxf(acc[t][1] + b1v, 0.f) * w1v;
        p_hi += fmaxf(acc[t][2] + b0v, 0.f) * w0v + fmaxf(acc[t][3] + b1v, 0.f) * w1v;
    }
    p_lo += __shfl_xor_sync(0xffffffffu, p_lo, 1);
    p_lo += __shfl_xor_sync(0xffffffffu, p_lo, 2);
    p_hi += __shfl_xor_sync(0xffffffffu, p_hi, 1);
    p_hi += __shfl_xor_sync(0xffffffffu, p_hi, 2);
    __syncthreads();
    float* s_head = (float*)smem_raw;  // 64 rows x 2 halves
    if (qc == 0) {
        s_head[(m0 + qr) * 2 + wx]     = p_lo;
        s_head[(m0 + qr + 8) * 2 + wx] = p_hi;
    }
    __syncthreads();
    if (tid < TILE_M) {
        int gr = row0 + tid;
        if (gr < n) {
            float z = s_head[tid * 2] + s_head[tid * 2 + 1] + bp2[0];
            out[gr] = 1.f / (1.f + expf(-z));
        }
    }
    // ---- safe cleanup (this kernel never reads these) ----
    int gt = blockIdx.x * 256 + tid;
    if (gt < Nn) d_deg[gt] = 0;
    if (gt < NB_SCAN) d_scan_state[gt] = 0ull;
    if (gt == 0) d_ticket = 0u;
}

// ---------------- CSR aggregation + fused per-graph sum/sumsq -----------------
__global__ void agg_kernel(const __half* __restrict__ T, const float* __restrict__ bias,
                           float* __restrict__ A,
                           float* __restrict__ gsum, float* __restrict__ gsq) {
    __shared__ __align__(16) float s_red[2][8][132];
    __shared__ int s_same, s_g;
    int tid = threadIdx.x;
    int wid = tid >> 5;
    int lane = tid & 31;
    int node = blockIdx.x * 8 + wid;
    if (tid == 0) {
        int g0 = d_batch[blockIdx.x * 8];
        int g7 = d_batch[blockIdx.x * 8 + 7];
        s_same = (g0 == g7);
        s_g = g0;
    }
    int s = d_rowptr[node], e = d_rowptr[node + 1];
    float ax = 0.f, ay = 0.f, az = 0.f, aw = 0.f;
    int p = s;
    for (; p + 4 <= e; p += 4) {
        int2 e0 = d_colw[p], e1 = d_colw[p + 1], e2 = d_colw[p + 2], e3 = d_colw[p + 3];
        float w0 = __int_as_float(e0.y), w1 = __int_as_float(e1.y);
        float w2 = __int_as_float(e2.y), w3 = __int_as_float(e3.y);
        uint2 u0 = ((const uint2*)(T + (size_t)e0.x * 128))[lane];
        uint2 u1 = ((const uint2*)(T + (size_t)e1.x * 128))[lane];
        uint2 u2 = ((const uint2*)(T + (size_t)e2.x * 128))[lane];
        uint2 u3 = ((const uint2*)(T + (size_t)e3.x * 128))[lane];
        float2 a0 = __half22float2(*(__half2*)&u0.x), b0 = __half22float2(*(__half2*)&u0.y);
        float2 a1 = __half22float2(*(__half2*)&u1.x), b1 = __half22float2(*(__half2*)&u1.y);
        float2 a2 = __half22float2(*(__half2*)&u2.x), b2 = __half22float2(*(__half2*)&u2.y);
        float2 a3 = __half22float2(*(__half2*)&u3.x), b3 = __half22float2(*(__half2*)&u3.y);
        ax += w0 * a0.x + w1 * a1.x + w2 * a2.x + w3 * a3.x;
        ay += w0 * a0.y + w1 * a1.y + w2 * a2.y + w3 * a3.y;
        az += w0 * b0.x + w1 * b1.x + w2 * b2.x + w3 * b3.x;
        aw += w0 * b0.y + w1 * b1.y + w2 * b2.y + w3 * b3.y;
    }
    for (; p < e; p++) {
        int2 ec = d_colw[p];
        float w = __int_as_float(ec.y);
        uint2 u = ((const uint2*)(T + (size_t)ec.x * 128))[lane];
        float2 a = __half22float2(*(__half2*)&u.x), b = __half22float2(*(__half2*)&u.y);
        ax += w * a.x; ay += w * a.y; az += w * b.x; aw += w * b.y;
    }
    float ds = d_dis[node];
    float sl = ds * ds;
    uint2 ut = ((const uint2*)(T + (size_t)node * 128))[lane];
    float2 ta = __half22float2(*(__half2*)&ut.x), tb = __half22float2(*(__half2*)&ut.y);
    float4 bb = *(const float4*)&bias[lane * 4];
    float4 o;
    o.x = ax + sl * ta.x + bb.x;
    o.y = ay + sl * ta.y + bb.y;
    o.z = az + sl * tb.x + bb.z;
    o.w = aw + sl * tb.y + bb.w;
    *(float4*)&A[(size_t)node * 128 + lane * 4] = o;

    *(float4*)&s_red[0][wid][lane * 4] = o;
    float4 o2 = make_float4(o.x * o.x, o.y * o.y, o.z * o.z, o.w * o.w);
    *(float4*)&s_red[1][wid][lane * 4] = o2;
    __syncthreads();
    if (s_same) {
        if (tid < 128) {
            float t1 = 0.f, t2 = 0.f;
#pragma unroll
            for (int k = 0; k < 8; k++) { t1 += s_red[0][k][tid]; t2 += s_red[1][k][tid]; }
            atomicAdd(&gsum[s_g * 128 + tid], t1);
            atomicAdd(&gsq[s_g * 128 + tid], t2);
        }
    } else {
        int g = d_batch[node];
        atomicAdd(&gsum[g * 128 + lane * 4 + 0], o.x);
        atomicAdd(&gsum[g * 128 + lane * 4 + 1], o.y);
        atomicAdd(&gsum[g * 128 + lane * 4 + 2], o.z);
        atomicAdd(&gsum[g * 128 + lane * 4 + 3], o.w);
        atomicAdd(&gsq[g * 128 + lane * 4 + 0], o2.x);
        atomicAdd(&gsq[g * 128 + lane * 4 + 1], o2.y);
        atomicAdd(&gsq[g * 128 + lane * 4 + 2], o2.z);
        atomicAdd(&gsq[g * 128 + lane * 4 + 3], o2.w);
    }
}

// out(fp16) = [in(fp16) +] relu((A - alpha*mean)*rsqrt(var+eps)*gamma + beta)
template <int RES>
__global__ void final_kernel(const float* __restrict__ A, const __half* __restrict__ in,
                             const float* __restrict__ alpha, const float* __restrict__ gamma,
                             const float* __restrict__ beta, __half* __restrict__ out,
                             const float* __restrict__ gsum, const float* __restrict__ gsq) {
    int idx = blockIdx.x * blockDim.x + threadIdx.x;  // over N*32 groups of 4
    if (idx >= Nn * 32) return;
    int node = idx >> 5;
    int q = idx & 31;
    int g = d_batch[node];
    float inv = 1.f / d_gcntf[g];
    float4 a  = ((const float4*)A)[idx];
    float4 gs = *(const float4*)&gsum[g * 128 + q * 4];
    float4 gq = *(const float4*)&gsq[g * 128 + q * 4];
    float4 al = *(const float4*)&alpha[q * 4];
    float4 ga = *(const float4*)&gamma[q * 4];
    float4 be = *(const float4*)&beta[q * 4];
    float4 m, vv, o;
    m.x = gs.x * inv; m.y = gs.y * inv; m.z = gs.z * inv; m.w = gs.w * inv;
    vv.x = gq.x * inv - m.x * m.x * al.x * (2.f - al.x);
    vv.y = gq.y * inv - m.y * m.y * al.y * (2.f - al.y);
    vv.z = gq.z * inv - m.z * m.z * al.z * (2.f - al.z);
    vv.w = gq.w * inv - m.w * m.w * al.w * (2.f - al.w);
    o.x = fmaxf((a.x - al.x * m.x) * rsqrtf(vv.x + EPSc) * ga.x + be.x, 0.f);
    o.y = fmaxf((a.y - al.y * m.y) * rsqrtf(vv.y + EPSc) * ga.y + be.y, 0.f);
    o.z = fmaxf((a.z - al.z * m.z) * rsqrtf(vv.z + EPSc) * ga.z + be.z, 0.f);
    o.w = fmaxf((a.w - al.w * m.w) * rsqrtf(vv.w + EPSc) * ga.w + be.w, 0.f);
    if (RES) {
        uint2 r = ((const uint2*)in)[idx];
        float2 r0 = __half22float2(*(__half2*)&r.x);
        float2 r1 = __half22float2(*(__half2*)&r.y);
        o.x += r0.x; o.y += r0.y; o.z += r1.x; o.w += r1.y;
    }
    ((uint2*)out)[idx] = f4_to_h4(o);
}

// ---------------- host orchestration ----------------
extern "C" void kernel_launch(void* const* d_in, const int* in_sizes, int n_in,
                              void* d_out, int out_size) {
    const float* x   = (const float*)d_in[0];
    const void*  ei  = d_in[1];
    const void*  bt  = d_in[2];
    const float* W1  = (const float*)d_in[3];
    const float* b1  = (const float*)d_in[4];
    const float* a1  = (const float*)d_in[5];
    const float* g1  = (const float*)d_in[6];
    const float* be1 = (const float*)d_in[7];
    const float* Wm  = (const float*)d_in[8];
    const float* bm  = (const float*)d_in[9];
    const float* am  = (const float*)d_in[10];
    const float* gm  = (const float*)d_in[11];
    const float* bem = (const float*)d_in[12];
    const float* WL  = (const float*)d_in[13];
    const float* bL  = (const float*)d_in[14];
    const float* aL  = (const float*)d_in[15];
    const float* gL  = (const float*)d_in[16];
    const float* beL = (const float*)d_in[17];
    const float* Wp1 = (const float*)d_in[18];
    const float* bp1 = (const float*)d_in[19];
    const float* Wp2 = (const float*)d_in[20];
    const float* bp2 = (const float*)d_in[21];
    float* out = (float*)d_out;

    float *A, *GS, *GQ;
    __half *HAh, *HBh, *Th, *Wh;
    cudaGetSymbolAddress((void**)&HAh, d_HAh);
    cudaGetSymbolAddress((void**)&HBh, d_HBh);
    cudaGetSymbolAddress((void**)&Th,  d_Th);
    cudaGetSymbolAddress((void**)&A,   d_A);
    cudaGetSymbolAddress((void**)&GS,  d_gsum);
    cudaGetSymbolAddress((void**)&GQ,  d_gsq);
    cudaGetSymbolAddress((void**)&Wh,  d_Wh);

    // side stream + fork/join events (created once, on the correctness call;
    // streams/events are not device-memory allocations)
    static cudaStream_t s1 = nullptr;
    static cudaEvent_t evF = nullptr, evJ = nullptr;
    if (s1 == nullptr) {
        cudaStreamCreateWithFlags(&s1, cudaStreamNonBlocking);
        cudaEventCreateWithFlags(&evF, cudaEventDisableTiming);
        cudaEventCreateWithFlags(&evJ, cudaEventDisableTiming);
    }

    const int smem = GEMM_SMEM;
    cudaFuncSetAttribute(gemm_fp16_half_kernel<float>,  cudaFuncAttributeMaxDynamicSharedMemorySize, smem);
    cudaFuncSetAttribute(gemm_fp16_half_kernel<__half>, cudaFuncAttributeMaxDynamicSharedMemorySize, smem);
    cudaFuncSetAttribute(gemm_fp16_head_kernel, cudaFuncAttributeMaxDynamicSharedMemorySize, smem);

    const int gemm_grid = (Nn + TILE_M - 1) / TILE_M;  // 782
    const int agg_grid  = Nn / 8;   // 6250, exact
    const int elem_grid = (Nn * 32 + 511) / 512;
    const int GL = NGg * Hh;
    const int WSZ = Hh * Hh;

    // ---- fork: preprocessing chain on s1, W1-convert + layer-1 GEMM on s0 ----
    cudaEventRecord(evF, 0);
    cudaStreamWaitEvent(s1, evF, 0);

    // s1: CSR construction (independent of GEMM path)
    hist_kernel<<<1024, 256, 0, s1>>>(ei, bt);
    scan_fused_kernel<<<NB_SCAN, 256, 0, s1>>>();
    scatter_kernel<<<(Ee + 255) / 256, 256, 0, s1>>>(ei);  // also zeroes gsum/gsq
    cudaEventRecord(evJ, s1);

    // s0 (default): W1 -> fp16, layer-1 GEMM, then remaining weights
    convert_w1_kernel<<<16, 256>>>(W1);
    gemm_fp16_half_kernel<float><<<gemm_grid, 256, smem>>>(x, Wh + 0 * WSZ, Th, Nn);
    convert_wrest_kernel<<<64, 256>>>(Wm, WL, Wp1);  // done long before layer-2 GEMM

    // join before the first aggregation
    cudaStreamWaitEvent(0, evJ, 0);

    // ---- layer 1 aggregate + norm -> HBh ----
    agg_kernel<<<agg_grid, 256>>>(Th, b1, A, GS + 0 * GL, GQ + 0 * GL);
    final_kernel<0><<<elem_grid, 512>>>(A, nullptr, a1, g1, be1, HBh, GS + 0 * GL, GQ + 0 * GL);

    // ---- mid layer 0 (residual): HBh -> HAh ----
    gemm_fp16_half_kernel<__half><<<gemm_grid, 256, smem>>>(HBh, Wh + 1 * WSZ, Th, Nn);
    agg_kernel<<<agg_grid, 256>>>(Th, bm + 0 * 128, A, GS + 1 * GL, GQ + 1 * GL);
    final_kernel<1><<<elem_grid, 512>>>(A, HBh, am + 0 * 128, gm + 0 * 128, bem + 0 * 128, HAh,
                                        GS + 1 * GL, GQ + 1 * GL);

    // ---- mid layer 1 (residual): HAh -> HBh ----
    gemm_fp16_half_kernel<__half><<<gemm_grid, 256, smem>>>(HAh, Wh + 2 * WSZ, Th, Nn);
    agg_kernel<<<agg_grid, 256>>>(Th, bm + 1 * 128, A, GS + 2 * GL, GQ + 2 * GL);
    final_kernel<1><<<elem_grid, 512>>>(A, HAh, am + 1 * 128, gm + 1 * 128, bem + 1 * 128, HBh,
                                        GS + 2 * GL, GQ + 2 * GL);

    // ---- last layer: HBh -> HAh ----
    gemm_fp16_half_kernel<__half><<<gemm_grid, 256, smem>>>(HBh, Wh + 3 * WSZ, Th, Nn);
    agg_kernel<<<agg_grid, 256>>>(Th, bL, A, GS + 3 * GL, GQ + 3 * GL);
    final_kernel<0><<<elem_grid, 512>>>(A, nullptr, aL, gL, beL, HAh, GS + 3 * GL, GQ + 3 * GL);

    // ---- predictor: HAh -> out (GEMM + fused head + safe cleanup) ----
    gemm_fp16_head_kernel<<<gemm_grid, 256, smem>>>(HAh, Wh + 4 * WSZ, bp1, Wp2, bp2, out, Nn);
}

// round 15
// speedup vs baseline: 1.0583x; 1.0152x over previous
#include <cuda_runtime.h>
#include <cuda_fp16.h>
#include <math.h>

#define Nn 50000
#define Hh 128
#define Ee 800000
#define NGg 64
#define EPSc 1e-5f
#define NB_SCAN 196   // ceil(50000/256)

// ---------------- device scratch (static globals; no allocation) ----------------
// All mutable state is zero at module load. Cleanup split to avoid races:
//  - d_gsum/d_gsq: zeroed by scatter_kernel (before any agg of the same run).
//  - d_deg/d_scan_state/d_ticket: zeroed by gemm_head epilogue (head never
//    reads them; next run's hist/scan are separate launches).
__device__ int    d_batch[Nn];
__device__ int    d_deg[Nn];
__device__ float  d_dis[Nn];
__device__ int    d_rowptr[Nn + 1];
__device__ int    d_cursor[Nn];
__device__ int2   d_colw[Ee];
__device__ unsigned long long d_scan_state[NB_SCAN];
__device__ unsigned d_ticket;
__device__ int    d_gstart[NGg + 1];
__device__ float  d_gcntf[NGg];
__device__ float  d_gsum[4 * NGg * Hh];
__device__ float  d_gsq[4 * NGg * Hh];
__device__ __half d_HAh[(size_t)Nn * Hh];   // fp16 hidden state A
__device__ __half d_HBh[(size_t)Nn * Hh];   // fp16 hidden state B
__device__ __half d_Th[(size_t)Nn * Hh];    // fp16 GEMM output (gather source)
__device__ __half d_Ah[(size_t)Nn * Hh];    // fp16 aggregated pre-norm
__device__ __half d_Wh[5 * Hh * Hh];        // fp16 weights: W1,Wm0,Wm1,WL,Wp1

__device__ __forceinline__ uint2 f4_to_h4(float4 v) {
    uint2 o;
    *(__half2*)&o.x = __floats2half2_rn(v.x, v.y);
    *(__half2*)&o.y = __floats2half2_rn(v.z, v.w);
    return o;
}
__device__ __forceinline__ float4 h4_to_f4(uint2 u) {
    float2 a = __half22float2(*(__half2*)&u.x);
    float2 b = __half22float2(*(__half2*)&u.y);
    return make_float4(a.x, a.y, b.x, b.y);
}

// ---------------- dtype detection (per-block, no global state) ----------------
__device__ __forceinline__ int detect_is64(const void* ei) {
    const long long* p = (const long long*)ei;
    int ok = 1;
#pragma unroll
    for (int k = 0; k < 16; k++) {
        long long v = p[k];
        if (v < 0 || v >= (long long)Nn) ok = 0;
    }
    return ok;
}

// ---------------- preprocessing ----------------

// convert ONLY W1 to fp16 (critical path before gemm_l1): 16 blocks
__global__ void convert_w1_kernel(const float* __restrict__ W1) {
    int i = blockIdx.x * blockDim.x + threadIdx.x;  // over 4096 float4 groups
    if (i >= 4096) return;
    ((uint2*)d_Wh)[i] = f4_to_h4(((const float4*)W1)[i]);
}

// convert the remaining 4 weight matrices (off the critical path)
__global__ void convert_wrest_kernel(const float* __restrict__ Wm,
                                     const float* __restrict__ WL,
                                     const float* __restrict__ Wp1) {
    int i = blockIdx.x * blockDim.x + threadIdx.x;  // over 4*4096 float4 groups
    if (i >= 4 * 4096) return;
    int m = i >> 12;
    int j = i & 4095;
    const float* src;
    switch (m) {
        case 0: src = Wm; break;
        case 1: src = Wm + 16384; break;
        case 2: src = WL; break;
        default: src = Wp1; break;
    }
    ((uint2*)d_Wh)[4096 + i] = f4_to_h4(((const float4*)src)[j]);
}

// batch convert + dst-degree histogram (stream 1)
__global__ void hist_kernel(const void* ei, const void* bt) {
    __shared__ int s_is64;
    if (threadIdx.x == 0) s_is64 = detect_is64(ei);
    __syncthreads();
    int is64 = s_is64;
    int gtid = blockIdx.x * blockDim.x + threadIdx.x;
    int stride = gridDim.x * blockDim.x;
    for (int i = gtid; i < Ee; i += stride) {
        int v = is64 ? (int)((const long long*)ei)[Ee + i] : ((const int*)ei)[Ee + i];
        atomicAdd(&d_deg[v], 1);
    }
    for (int i = gtid; i < Nn; i += stride) {
        int v = is64 ? (int)((const long long*)bt)[i] : ((const int*)bt)[i];
        d_batch[i] = v;
    }
}

// decoupled-lookback scan of d_deg -> rowptr/cursor/dis + per-graph ranges
__global__ void scan_fused_kernel() {
    __shared__ unsigned sbid;
    __shared__ int s_excl;
    __shared__ int sh[256];
    if (threadIdx.x == 0) sbid = atomicAdd(&d_ticket, 1u);
    __syncthreads();
    int b = (int)sbid;
    int idx = b * 256 + threadIdx.x;
    int deg = (idx < Nn) ? d_deg[idx] : 0;
    sh[threadIdx.x] = deg;
    __syncthreads();
    for (int off = 1; off < 256; off <<= 1) {
        int u = 0;
        if (threadIdx.x >= off) u = sh[threadIdx.x - off];
        __syncthreads();
        if (threadIdx.x >= off) sh[threadIdx.x] += u;
        __syncthreads();
    }
    int incl = sh[threadIdx.x];
    int aggr = sh[255];
    if (threadIdx.x == 0) {
        if (b == 0) {
            atomicExch(&d_scan_state[0], (2ull << 32) | (unsigned)aggr);
            s_excl = 0;
        } else {
            atomicExch(&d_scan_state[b], (1ull << 32) | (unsigned)aggr);
            int excl = 0;
            int j = b - 1;
            while (true) {
                unsigned long long st;
                do { st = atomicAdd(&d_scan_state[j], 0ull); } while ((st >> 32) == 0ull);
                excl += (int)(unsigned)st;
                if ((st >> 32) == 2ull) break;
                j--;
            }
            atomicExch(&d_scan_state[b], (2ull << 32) | (unsigned)(excl + aggr));
            s_excl = excl;
        }
    }
    __syncthreads();
    int excl = s_excl;
    if (idx < Nn) {
        d_rowptr[idx + 1] = excl + incl;
        if (idx == 0) d_rowptr[0] = 0;
        d_cursor[idx] = excl + incl - deg;
        d_dis[idx] = rsqrtf((float)deg + 1.0f);
    }
    if (b == 0) {
        int t = threadIdx.x;
        if (t <= NGg) {
            int lo = 0, hi = Nn;
            while (lo < hi) {
                int mid = (lo + hi) >> 1;
                if (d_batch[mid] < t) lo = mid + 1; else hi = mid;
            }
            d_gstart[t] = lo;
        }
        __syncthreads();
        if (t < NGg) {
            int c = d_gstart[t + 1] - d_gstart[t];
            d_gcntf[t] = (c > 0) ? (float)c : 1.0f;
        }
    }
}

// scatter edges into CSR + zero gsum/gsq accumulators for this run
__global__ void scatter_kernel(const void* ei) {
    __shared__ int s_is64;
    if (threadIdx.x == 0) s_is64 = detect_is64(ei);
    __syncthreads();
    int i = blockIdx.x * blockDim.x + threadIdx.x;
    if (i < 4 * NGg * Hh) { d_gsum[i] = 0.f; d_gsq[i] = 0.f; }
    if (i >= Ee) return;
    int s, dd;
    if (s_is64) {
        s  = (int)((const long long*)ei)[i];
        dd = (int)((const long long*)ei)[Ee + i];
    } else {
        s  = ((const int*)ei)[i];
        dd = ((const int*)ei)[Ee + i];
    }
    int pos = atomicAdd(&d_cursor[dd], 1);
    d_colw[pos] = make_int2(s, __float_as_int(d_dis[s] * d_dis[dd]));
}

// ---------------- fp16 tensor-core GEMM (ldmatrix + mma.m16n8k16) -------------
// Y[n,128] = X[n,128] @ W[128,128]; fp16 operands, fp32 accumulate.
// 256 threads = 8 warps: wy=warp&3 -> rows wy*16..+15 ; wx=warp>>2 -> cols wx*64..+63
#define XPITCH 136
#define WPITCH 136
#define TILE_M 64
#define GEMM_SMEM ((TILE_M * XPITCH + 128 * WPITCH) * 2)

__device__ __forceinline__ void ldm_x4(unsigned& r0, unsigned& r1, unsigned& r2,
                                       unsigned& r3, unsigned addr) {
    asm volatile("ldmatrix.sync.aligned.m8n8.x4.shared.b16 {%0,%1,%2,%3}, [%4];"
                 : "=r"(r0), "=r"(r1), "=r"(r2), "=r"(r3) : "r"(addr));
}
__device__ __forceinline__ void ldm_x4t(unsigned& r0, unsigned& r1, unsigned& r2,
                                        unsigned& r3, unsigned addr) {
    asm volatile("ldmatrix.sync.aligned.m8n8.x4.trans.shared.b16 {%0,%1,%2,%3}, [%4];"
                 : "=r"(r0), "=r"(r1), "=r"(r2), "=r"(r3) : "r"(addr));
}

// stage X tile: fp32 source (layer 1) — convert
__device__ __forceinline__ void stage_X(const float* __restrict__ X, __half* Xs,
                                        int row0, int n, int tid) {
#pragma unroll
    for (int i = 0; i < 8; i++) {
        int idx = i * 256 + tid;
        int r = idx >> 5;
        int c = (idx & 31) * 4;
        float4 xv = make_float4(0.f, 0.f, 0.f, 0.f);
        if (row0 + r < n) xv = *(const float4*)&X[(size_t)(row0 + r) * 128 + c];
        *(uint2*)&Xs[r * XPITCH + c] = f4_to_h4(xv);
    }
}
// stage X tile: fp16 source — straight copy (uint4 = 8 halves)
__device__ __forceinline__ void stage_X(const __half* __restrict__ X, __half* Xs,
                                        int row0, int n, int tid) {
#pragma unroll
    for (int i = 0; i < 4; i++) {
        int idx = i * 256 + tid;
        int r = idx >> 4;
        int c = (idx & 15) * 8;
        uint4 v = make_uint4(0u, 0u, 0u, 0u);
        if (row0 + r < n) v = *(const uint4*)&X[(size_t)(row0 + r) * 128 + c];
        *(uint4*)&Xs[r * XPITCH + c] = v;
    }
}
// stage W (always fp16): 128x128 halves, straight copy
__device__ __forceinline__ void stage_W(const __half* __restrict__ W, __half* Ws, int tid) {
#pragma unroll
    for (int i = 0; i < 8; i++) {
        int idx = i * 256 + tid;
        int r = idx >> 4;
        int c = (idx & 15) * 8;
        *(uint4*)&Ws[r * WPITCH + c] = *(const uint4*)&W[r * 128 + c];
    }
}

#define FP16_GEMM_CORE()                                                          \
    extern __shared__ __align__(16) char smem_raw[];                              \
    __half* Xs = (__half*)smem_raw;                                               \
    __half* Ws = Xs + TILE_M * XPITCH;                                            \
    const int tid = threadIdx.x;                                                  \
    const int row0 = blockIdx.x * TILE_M;                                         \
    stage_W(W, Ws, tid);                                                          \
    stage_X(X, Xs, row0, n, tid);                                                 \
    __syncthreads();                                                              \
    const int warp = tid >> 5;                                                    \
    const int lane = tid & 31;                                                    \
    const int qr = lane >> 2;                                                     \
    const int qc = lane & 3;                                                      \
    const int wy = warp & 3;                                                      \
    const int wx = warp >> 2;                                                     \
    const int m0 = wy * 16;                                                       \
    const int n0 = wx * 64;                                                       \
    const int trow = lane & 7;                                                    \
    const int tsel = lane >> 3;                                                   \
    unsigned xs_b = (unsigned)__cvta_generic_to_shared(Xs);                       \
    unsigned ws_b = (unsigned)__cvta_generic_to_shared(Ws);                       \
    unsigned a_addr = xs_b +                                                      \
        ((m0 + trow + 8 * (tsel & 1)) * XPITCH + 8 * (tsel >> 1)) * 2;            \
    unsigned b_addr = ws_b +                                                      \
        ((trow + 8 * (tsel & 1)) * WPITCH + n0 + 8 * (tsel >> 1)) * 2;            \
    float acc[8][4];                                                              \
    _Pragma("unroll")                                                             \
    for (int t = 0; t < 8; t++) {                                                 \
        acc[t][0] = 0.f; acc[t][1] = 0.f; acc[t][2] = 0.f; acc[t][3] = 0.f;       \
    }                                                                             \
    _Pragma("unroll")                                                             \
    for (int ks = 0; ks < 8; ks++) {                                              \
        unsigned a0, a1, a2, a3;                                                  \
        ldm_x4(a0, a1, a2, a3, a_addr + ks * 32);                                 \
        _Pragma("unroll")                                                         \
        for (int tp = 0; tp < 4; tp++) {                                          \
            unsigned b0, b1, b2, b3;                                              \
            ldm_x4t(b0, b1, b2, b3, b_addr + ks * (16 * WPITCH * 2) + tp * 32);   \
            asm volatile(                                                         \
                "mma.sync.aligned.m16n8k16.row.col.f32.f16.f16.f32 "              \
                "{%0,%1,%2,%3}, {%4,%5,%6,%7}, {%8,%9}, {%0,%1,%2,%3};"           \
                : "+f"(acc[2 * tp][0]), "+f"(acc[2 * tp][1]),                     \
                  "+f"(acc[2 * tp][2]), "+f"(acc[2 * tp][3])                      \
                : "r"(a0), "r"(a1), "r"(a2), "r"(a3), "r"(b0), "r"(b1));          \
            asm volatile(                                                         \
                "mma.sync.aligned.m16n8k16.row.col.f32.f16.f16.f32 "              \
                "{%0,%1,%2,%3}, {%4,%5,%6,%7}, {%8,%9}, {%0,%1,%2,%3};"           \
                : "+f"(acc[2 * tp + 1][0]), "+f"(acc[2 * tp + 1][1]),             \
                  "+f"(acc[2 * tp + 1][2]), "+f"(acc[2 * tp + 1][3])              \
                : "r"(a0), "r"(a1), "r"(a2), "r"(a3), "r"(b2), "r"(b3));          \
        }                                                                         \
    }                                                                             \
    const int r_lo = row0 + m0 + qr;                                              \
    const int r_hi = r_lo + 8;

// fp16-output GEMM (feeds edge gather); input fp32 or fp16
template <typename TIn>
__global__ __launch_bounds__(256) void gemm_fp16_half_kernel(
    const TIn* __restrict__ X, const __half* __restrict__ W,
    __half* __restrict__ Y, int n) {
    FP16_GEMM_CORE()
    if (r_lo < n) {
#pragma unroll
        for (int t = 0; t < 8; t++)
            *(__half2*)&Y[(size_t)r_lo * 128 + n0 + t * 8 + qc * 2] =
                __floats2half2_rn(acc[t][0], acc[t][1]);
    }
    if (r_hi < n) {
#pragma unroll
        for (int t = 0; t < 8; t++)
            *(__half2*)&Y[(size_t)r_hi * 128 + n0 + t * 8 + qc * 2] =
                __floats2half2_rn(acc[t][2], acc[t][3]);
    }
}

// final GEMM with fused predictor head + safe state cleanup (fp16 input).
__global__ __launch_bounds__(256) void gemm_fp16_head_kernel(
    const __half* __restrict__ X, const __half* __restrict__ W,
    const float* __restrict__ bp1, const float* __restrict__ Wp2,
    const float* __restrict__ bp2, float* __restrict__ out, int n) {
    FP16_GEMM_CORE()
    float p_lo = 0.f, p_hi = 0.f;
#pragma unroll
    for (int t = 0; t < 8; t++) {
        int c = n0 + t * 8 + qc * 2;
        float b0v = bp1[c], b1v = bp1[c + 1];
        float w0v = Wp2[c], w1v = Wp2[c + 1];
        p_lo += fmaxf(acc[t][0] + b0v, 0.f) * w0v + fmaxf(acc[t][1] + b1v, 0.f) * w1v;
        p_hi += fmaxf(acc[t][2] + b0v, 0.f) * w0v + fmaxf(acc[t][3] + b1v, 0.f) * w1v;
    }
    p_lo += __shfl_xor_sync(0xffffffffu, p_lo, 1);
    p_lo += __shfl_xor_sync(0xffffffffu, p_lo, 2);
    p_hi += __shfl_xor_sync(0xffffffffu, p_hi, 1);
    p_hi += __shfl_xor_sync(0xffffffffu, p_hi, 2);
    __syncthreads();
    float* s_head = (float*)smem_raw;  // 64 rows x 2 halves
    if (qc == 0) {
        s_head[(m0 + qr) * 2 + wx]     = p_lo;
        s_head[(m0 + qr + 8) * 2 + wx] = p_hi;
    }
    __syncthreads();
    if (tid < TILE_M) {
        int gr = row0 + tid;
        if (gr < n) {
            float z = s_head[tid * 2] + s_head[tid * 2 + 1] + bp2[0];
            out[gr] = 1.f / (1.f + expf(-z));
        }
    }
    // ---- safe cleanup (this kernel never reads these) ----
    int gt = blockIdx.x * 256 + tid;
    if (gt < Nn) d_deg[gt] = 0;
    if (gt < NB_SCAN) d_scan_state[gt] = 0ull;
    if (gt == 0) d_ticket = 0u;
}

// ---------------- CSR aggregation + fused per-graph sum/sumsq -----------------
// A stored fp16 (rounded at store); gsum/gsq accumulated from fp32 values.
__global__ void agg_kernel(const __half* __restrict__ T, const float* __restrict__ bias,
                           __half* __restrict__ A,
                           float* __restrict__ gsum, float* __restrict__ gsq) {
    __shared__ __align__(16) float s_red[2][8][132];
    __shared__ int s_same, s_g;
    int tid = threadIdx.x;
    int wid = tid >> 5;
    int lane = tid & 31;
    int node = blockIdx.x * 8 + wid;
    if (tid == 0) {
        int g0 = d_batch[blockIdx.x * 8];
        int g7 = d_batch[blockIdx.x * 8 + 7];
        s_same = (g0 == g7);
        s_g = g0;
    }
    int s = d_rowptr[node], e = d_rowptr[node + 1];
    float ax = 0.f, ay = 0.f, az = 0.f, aw = 0.f;
    int p = s;
    for (; p + 4 <= e; p += 4) {
        int2 e0 = d_colw[p], e1 = d_colw[p + 1], e2 = d_colw[p + 2], e3 = d_colw[p + 3];
        float w0 = __int_as_float(e0.y), w1 = __int_as_float(e1.y);
        float w2 = __int_as_float(e2.y), w3 = __int_as_float(e3.y);
        uint2 u0 = ((const uint2*)(T + (size_t)e0.x * 128))[lane];
        uint2 u1 = ((const uint2*)(T + (size_t)e1.x * 128))[lane];
        uint2 u2 = ((const uint2*)(T + (size_t)e2.x * 128))[lane];
        uint2 u3 = ((const uint2*)(T + (size_t)e3.x * 128))[lane];
        float2 a0 = __half22float2(*(__half2*)&u0.x), b0 = __half22float2(*(__half2*)&u0.y);
        float2 a1 = __half22float2(*(__half2*)&u1.x), b1 = __half22float2(*(__half2*)&u1.y);
        float2 a2 = __half22float2(*(__half2*)&u2.x), b2 = __half22float2(*(__half2*)&u2.y);
        float2 a3 = __half22float2(*(__half2*)&u3.x), b3 = __half22float2(*(__half2*)&u3.y);
        ax += w0 * a0.x + w1 * a1.x + w2 * a2.x + w3 * a3.x;
        ay += w0 * a0.y + w1 * a1.y + w2 * a2.y + w3 * a3.y;
        az += w0 * b0.x + w1 * b1.x + w2 * b2.x + w3 * b3.x;
        aw += w0 * b0.y + w1 * b1.y + w2 * b2.y + w3 * b3.y;
    }
    for (; p < e; p++) {
        int2 ec = d_colw[p];
        float w = __int_as_float(ec.y);
        uint2 u = ((const uint2*)(T + (size_t)ec.x * 128))[lane];
        float2 a = __half22float2(*(__half2*)&u.x), b = __half22float2(*(__half2*)&u.y);
        ax += w * a.x; ay += w * a.y; az += w * b.x; aw += w * b.y;
    }
    float ds = d_dis[node];
    float sl = ds * ds;
    uint2 ut = ((const uint2*)(T + (size_t)node * 128))[lane];
    float2 ta = __half22float2(*(__half2*)&ut.x), tb = __half22float2(*(__half2*)&ut.y);
    float4 bb = *(const float4*)&bias[lane * 4];
    float4 o;
    o.x = ax + sl * ta.x + bb.x;
    o.y = ay + sl * ta.y + bb.y;
    o.z = az + sl * tb.x + bb.z;
    o.w = aw + sl * tb.y + bb.w;
    ((uint2*)(A + (size_t)node * 128))[lane] = f4_to_h4(o);

    *(float4*)&s_red[0][wid][lane * 4] = o;
    float4 o2 = make_float4(o.x * o.x, o.y * o.y, o.z * o.z, o.w * o.w);
    *(float4*)&s_red[1][wid][lane * 4] = o2;
    __syncthreads();
    if (s_same) {
        if (tid < 128) {
            float t1 = 0.f, t2 = 0.f;
#pragma unroll
            for (int k = 0; k < 8; k++) { t1 += s_red[0][k][tid]; t2 += s_red[1][k][tid]; }
            atomicAdd(&gsum[s_g * 128 + tid], t1);
            atomicAdd(&gsq[s_g * 128 + tid], t2);
        }
    } else {
        int g = d_batch[node];
        atomicAdd(&gsum[g * 128 + lane * 4 + 0], o.x);
        atomicAdd(&gsum[g * 128 + lane * 4 + 1], o.y);
        atomicAdd(&gsum[g * 128 + lane * 4 + 2], o.z);
        atomicAdd(&gsum[g * 128 + lane * 4 + 3], o.w);
        atomicAdd(&gsq[g * 128 + lane * 4 + 0], o2.x);
        atomicAdd(&gsq[g * 128 + lane * 4 + 1], o2.y);
        atomicAdd(&gsq[g * 128 + lane * 4 + 2], o2.z);
        atomicAdd(&gsq[g * 128 + lane * 4 + 3], o2.w);
    }
}

// out(fp16) = [in(fp16) +] relu((A(fp16) - alpha*mean)*rsqrt(var+eps)*gamma + beta)
template <int RES>
__global__ void final_kernel(const __half* __restrict__ A, const __half* __restrict__ in,
                             const float* __restrict__ alpha, const float* __restrict__ gamma,
                             const float* __restrict__ beta, __half* __restrict__ out,
                             const float* __restrict__ gsum, const float* __restrict__ gsq) {
    int idx = blockIdx.x * blockDim.x + threadIdx.x;  // over N*32 groups of 4
    if (idx >= Nn * 32) return;
    int node = idx >> 5;
    int q = idx & 31;
    int g = d_batch[node];
    float inv = 1.f / d_gcntf[g];
    float4 a  = h4_to_f4(((const uint2*)A)[idx]);
    float4 gs = *(const float4*)&gsum[g * 128 + q * 4];
    float4 gq = *(const float4*)&gsq[g * 128 + q * 4];
    float4 al = *(const float4*)&alpha[q * 4];
    float4 ga = *(const float4*)&gamma[q * 4];
    float4 be = *(const float4*)&beta[q * 4];
    float4 m, vv, o;
    m.x = gs.x * inv; m.y = gs.y * inv; m.z = gs.z * inv; m.w = gs.w * inv;
    vv.x = gq.x * inv - m.x * m.x * al.x * (2.f - al.x);
    vv.y = gq.y * inv - m.y * m.y * al.y * (2.f - al.y);
    vv.z = gq.z * inv - m.z * m.z * al.z * (2.f - al.z);
    vv.w = gq.w * inv - m.w * m.w * al.w * (2.f - al.w);
    o.x = fmaxf((a.x - al.x * m.x) * rsqrtf(vv.x + EPSc) * ga.x + be.x, 0.f);
    o.y = fmaxf((a.y - al.y * m.y) * rsqrtf(vv.y + EPSc) * ga.y + be.y, 0.f);
    o.z = fmaxf((a.z - al.z * m.z) * rsqrtf(vv.z + EPSc) * ga.z + be.z, 0.f);
    o.w = fmaxf((a.w - al.w * m.w) * rsqrtf(vv.w + EPSc) * ga.w + be.w, 0.f);
    if (RES) {
        uint2 r = ((const uint2*)in)[idx];
        float2 r0 = __half22float2(*(__half2*)&r.x);
        float2 r1 = __half22float2(*(__half2*)&r.y);
        o.x += r0.x; o.y += r0.y; o.z += r1.x; o.w += r1.y;
    }
    ((uint2*)out)[idx] = f4_to_h4(o);
}

// ---------------- host orchestration ----------------
extern "C" void kernel_launch(void* const* d_in, const int* in_sizes, int n_in,
                              void* d_out, int out_size) {
    const float* x   = (const float*)d_in[0];
    const void*  ei  = d_in[1];
    const void*  bt  = d_in[2];
    const float* W1  = (const float*)d_in[3];
    const float* b1  = (const float*)d_in[4];
    const float* a1  = (const float*)d_in[5];
    const float* g1  = (const float*)d_in[6];
    const float* be1 = (const float*)d_in[7];
    const float* Wm  = (const float*)d_in[8];
    const float* bm  = (const float*)d_in[9];
    const float* am  = (const float*)d_in[10];
    const float* gm  = (const float*)d_in[11];
    const float* bem = (const float*)d_in[12];
    const float* WL  = (const float*)d_in[13];
    const float* bL  = (const float*)d_in[14];
    const float* aL  = (const float*)d_in[15];
    const float* gL  = (const float*)d_in[16];
    const float* beL = (const float*)d_in[17];
    const float* Wp1 = (const float*)d_in[18];
    const float* bp1 = (const float*)d_in[19];
    const float* Wp2 = (const float*)d_in[20];
    const float* bp2 = (const float*)d_in[21];
    float* out = (float*)d_out;

    float *GS, *GQ;
    __half *HAh, *HBh, *Th, *Ah, *Wh;
    cudaGetSymbolAddress((void**)&HAh, d_HAh);
    cudaGetSymbolAddress((void**)&HBh, d_HBh);
    cudaGetSymbolAddress((void**)&Th,  d_Th);
    cudaGetSymbolAddress((void**)&Ah,  d_Ah);
    cudaGetSymbolAddress((void**)&GS,  d_gsum);
    cudaGetSymbolAddress((void**)&GQ,  d_gsq);
    cudaGetSymbolAddress((void**)&Wh,  d_Wh);

    // side stream + fork/join events (created once, on the correctness call;
    // streams/events are not device-memory allocations)
    static cudaStream_t s1 = nullptr;
    static cudaEvent_t evF = nullptr, evJ = nullptr;
    if (s1 == nullptr) {
        cudaStreamCreateWithFlags(&s1, cudaStreamNonBlocking);
        cudaEventCreateWithFlags(&evF, cudaEventDisableTiming);
        cudaEventCreateWithFlags(&evJ, cudaEventDisableTiming);
    }

    const int smem = GEMM_SMEM;
    cudaFuncSetAttribute(gemm_fp16_half_kernel<float>,  cudaFuncAttributeMaxDynamicSharedMemorySize, smem);
    cudaFuncSetAttribute(gemm_fp16_half_kernel<__half>, cudaFuncAttributeMaxDynamicSharedMemorySize, smem);
    cudaFuncSetAttribute(gemm_fp16_head_kernel, cudaFuncAttributeMaxDynamicSharedMemorySize, smem);

    const int gemm_grid = (Nn + TILE_M - 1) / TILE_M;  // 782
    const int agg_grid  = Nn / 8;   // 6250, exact
    const int elem_grid = (Nn * 32 + 511) / 512;
    const int GL = NGg * Hh;
    const int WSZ = Hh * Hh;

    // ---- fork: preprocessing chain on s1, W1-convert + layer-1 GEMM on s0 ----
    cudaEventRecord(evF, 0);
    cudaStreamWaitEvent(s1, evF, 0);

    // s1: CSR construction (independent of GEMM path)
    hist_kernel<<<1024, 256, 0, s1>>>(ei, bt);
    scan_fused_kernel<<<NB_SCAN, 256, 0, s1>>>();
    scatter_kernel<<<(Ee + 255) / 256, 256, 0, s1>>>(ei);  // also zeroes gsum/gsq
    cudaEventRecord(evJ, s1);

    // s0 (default): W1 -> fp16, layer-1 GEMM, then remaining weights
    convert_w1_kernel<<<16, 256>>>(W1);
    gemm_fp16_half_kernel<float><<<gemm_grid, 256, smem>>>(x, Wh + 0 * WSZ, Th, Nn);
    convert_wrest_kernel<<<64, 256>>>(Wm, WL, Wp1);  // done long before layer-2 GEMM

    // join before the first aggregation
    cudaStreamWaitEvent(0, evJ, 0);

    // ---- layer 1 aggregate + norm -> HBh ----
    agg_kernel<<<agg_grid, 256>>>(Th, b1, Ah, GS + 0 * GL, GQ + 0 * GL);
    final_kernel<0><<<elem_grid, 512>>>(Ah, nullptr, a1, g1, be1, HBh, GS + 0 * GL, GQ + 0 * GL);

    // ---- mid layer 0 (residual): HBh -> HAh ----
    gemm_fp16_half_kernel<__half><<<gemm_grid, 256, smem>>>(HBh, Wh + 1 * WSZ, Th, Nn);
    agg_kernel<<<agg_grid, 256>>>(Th, bm + 0 * 128, Ah, GS + 1 * GL, GQ + 1 * GL);
    final_kernel<1><<<elem_grid, 512>>>(Ah, HBh, am + 0 * 128, gm + 0 * 128, bem + 0 * 128, HAh,
                                        GS + 1 * GL, GQ + 1 * GL);

    // ---- mid layer 1 (residual): HAh -> HBh ----
    gemm_fp16_half_kernel<__half><<<gemm_grid, 256, smem>>>(HAh, Wh + 2 * WSZ, Th, Nn);
    agg_kernel<<<agg_grid, 256>>>(Th, bm + 1 * 128, Ah, GS + 2 * GL, GQ + 2 * GL);
    final_kernel<1><<<elem_grid, 512>>>(Ah, HAh, am + 1 * 128, gm + 1 * 128, bem + 1 * 128, HBh,
                                        GS + 2 * GL, GQ + 2 * GL);

    // ---- last layer: HBh -> HAh ----
    gemm_fp16_half_kernel<__half><<<gemm_grid, 256, smem>>>(HBh, Wh + 3 * WSZ, Th, Nn);
    agg_kernel<<<agg_grid, 256>>>(Th, bL, Ah, GS + 3 * GL, GQ + 3 * GL);
    final_kernel<0><<<elem_grid, 512>>>(Ah, nullptr, aL, gL, beL, HAh, GS + 3 * GL, GQ + 3 * GL);

    // ---- predictor: HAh -> out (GEMM + fused head + safe cleanup) ----
    gemm_fp16_head_kernel<<<gemm_grid, 256, smem>>>(HAh, Wh + 4 * WSZ, bp1, Wp2, bp2, out, Nn);
}

// round 16
// speedup vs baseline: 1.0817x; 1.0221x over previous
#include <cuda_runtime.h>
#include <cuda_fp16.h>
#include <math.h>

#define Nn 50000
#define Hh 128
#define Ee 800000
#define NGg 64
#define EPSc 1e-5f
#define NB_SCAN 196   // ceil(50000/256)

// ---------------- device scratch (static globals; no allocation) ----------------
// All mutable state is zero at module load. Cleanup split to avoid races:
//  - d_gsum/d_gsq: zeroed by scatter_kernel (before any agg of the same run).
//  - d_deg/d_scan_state/d_ticket: zeroed by gemm_head epilogue (head never
//    reads them; next run's hist/scan are separate launches).
__device__ int    d_batch[Nn];
__device__ int    d_deg[Nn];
__device__ float  d_dis[Nn];
__device__ int    d_rowptr[Nn + 1];
__device__ int    d_cursor[Nn];
__device__ int2   d_colw[Ee];
__device__ unsigned long long d_scan_state[NB_SCAN];
__device__ unsigned d_ticket;
__device__ int    d_gstart[NGg + 1];
__device__ float  d_gcntf[NGg];
__device__ float  d_gsum[4 * NGg * Hh];
__device__ float  d_gsq[4 * NGg * Hh];
__device__ __half d_HAh[(size_t)Nn * Hh];   // fp16 hidden state A
__device__ __half d_HBh[(size_t)Nn * Hh];   // fp16 hidden state B
__device__ __half d_Th[(size_t)Nn * Hh];    // fp16 GEMM output (gather source)
__device__ __half d_Ah[(size_t)Nn * Hh];    // fp16 aggregated pre-norm
__device__ __half d_Wh[5 * Hh * Hh];        // fp16 weights: W1,Wm0,Wm1,WL,Wp1

__device__ __forceinline__ uint2 f4_to_h4(float4 v) {
    uint2 o;
    *(__half2*)&o.x = __floats2half2_rn(v.x, v.y);
    *(__half2*)&o.y = __floats2half2_rn(v.z, v.w);
    return o;
}
__device__ __forceinline__ float4 h4_to_f4(uint2 u) {
    float2 a = __half22float2(*(__half2*)&u.x);
    float2 b = __half22float2(*(__half2*)&u.y);
    return make_float4(a.x, a.y, b.x, b.y);
}

// ---------------- dtype detection (per-block, no global state) ----------------
__device__ __forceinline__ int detect_is64(const void* ei) {
    const long long* p = (const long long*)ei;
    int ok = 1;
#pragma unroll
    for (int k = 0; k < 16; k++) {
        long long v = p[k];
        if (v < 0 || v >= (long long)Nn) ok = 0;
    }
    return ok;
}

// ---------------- preprocessing ----------------

// convert ONLY W1 to fp16 (critical path before gemm_l1): 16 blocks
__global__ void convert_w1_kernel(const float* __restrict__ W1) {
    int i = blockIdx.x * blockDim.x + threadIdx.x;  // over 4096 float4 groups
    if (i >= 4096) return;
    ((uint2*)d_Wh)[i] = f4_to_h4(((const float4*)W1)[i]);
}

// convert the remaining 4 weight matrices (off the critical path)
__global__ void convert_wrest_kernel(const float* __restrict__ Wm,
                                     const float* __restrict__ WL,
                                     const float* __restrict__ Wp1) {
    int i = blockIdx.x * blockDim.x + threadIdx.x;  // over 4*4096 float4 groups
    if (i >= 4 * 4096) return;
    int m = i >> 12;
    int j = i & 4095;
    const float* src;
    switch (m) {
        case 0: src = Wm; break;
        case 1: src = Wm + 16384; break;
        case 2: src = WL; break;
        default: src = Wp1; break;
    }
    ((uint2*)d_Wh)[4096 + i] = f4_to_h4(((const float4*)src)[j]);
}

// batch convert + dst-degree histogram (stream 1)
__global__ void hist_kernel(const void* ei, const void* bt) {
    __shared__ int s_is64;
    if (threadIdx.x == 0) s_is64 = detect_is64(ei);
    __syncthreads();
    int is64 = s_is64;
    int gtid = blockIdx.x * blockDim.x + threadIdx.x;
    int stride = gridDim.x * blockDim.x;
    for (int i = gtid; i < Ee; i += stride) {
        int v = is64 ? (int)((const long long*)ei)[Ee + i] : ((const int*)ei)[Ee + i];
        atomicAdd(&d_deg[v], 1);
    }
    for (int i = gtid; i < Nn; i += stride) {
        int v = is64 ? (int)((const long long*)bt)[i] : ((const int*)bt)[i];
        d_batch[i] = v;
    }
}

// decoupled-lookback scan of d_deg -> rowptr/cursor/dis + per-graph ranges
__global__ void scan_fused_kernel() {
    __shared__ unsigned sbid;
    __shared__ int s_excl;
    __shared__ int sh[256];
    if (threadIdx.x == 0) sbid = atomicAdd(&d_ticket, 1u);
    __syncthreads();
    int b = (int)sbid;
    int idx = b * 256 + threadIdx.x;
    int deg = (idx < Nn) ? d_deg[idx] : 0;
    sh[threadIdx.x] = deg;
    __syncthreads();
    for (int off = 1; off < 256; off <<= 1) {
        int u = 0;
        if (threadIdx.x >= off) u = sh[threadIdx.x - off];
        __syncthreads();
        if (threadIdx.x >= off) sh[threadIdx.x] += u;
        __syncthreads();
    }
    int incl = sh[threadIdx.x];
    int aggr = sh[255];
    if (threadIdx.x == 0) {
        if (b == 0) {
            atomicExch(&d_scan_state[0], (2ull << 32) | (unsigned)aggr);
            s_excl = 0;
        } else {
            atomicExch(&d_scan_state[b], (1ull << 32) | (unsigned)aggr);
            int excl = 0;
            int j = b - 1;
            while (true) {
                unsigned long long st;
                do { st = atomicAdd(&d_scan_state[j], 0ull); } while ((st >> 32) == 0ull);
                excl += (int)(unsigned)st;
                if ((st >> 32) == 2ull) break;
                j--;
            }
            atomicExch(&d_scan_state[b], (2ull << 32) | (unsigned)(excl + aggr));
            s_excl = excl;
        }
    }
    __syncthreads();
    int excl = s_excl;
    if (idx < Nn) {
        d_rowptr[idx + 1] = excl + incl;
        if (idx == 0) d_rowptr[0] = 0;
        d_cursor[idx] = excl + incl - deg;
        d_dis[idx] = rsqrtf((float)deg + 1.0f);
    }
    if (b == 0) {
        int t = threadIdx.x;
        if (t <= NGg) {
            int lo = 0, hi = Nn;
            while (lo < hi) {
                int mid = (lo + hi) >> 1;
                if (d_batch[mid] < t) lo = mid + 1; else hi = mid;
            }
            d_gstart[t] = lo;
        }
        __syncthreads();
        if (t < NGg) {
            int c = d_gstart[t + 1] - d_gstart[t];
            d_gcntf[t] = (c > 0) ? (float)c : 1.0f;
        }
    }
}

// scatter edges into CSR + zero gsum/gsq accumulators for this run
__global__ void scatter_kernel(const void* ei) {
    __shared__ int s_is64;
    if (threadIdx.x == 0) s_is64 = detect_is64(ei);
    __syncthreads();
    int i = blockIdx.x * blockDim.x + threadIdx.x;
    if (i < 4 * NGg * Hh) { d_gsum[i] = 0.f; d_gsq[i] = 0.f; }
    if (i >= Ee) return;
    int s, dd;
    if (s_is64) {
        s  = (int)((const long long*)ei)[i];
        dd = (int)((const long long*)ei)[Ee + i];
    } else {
        s  = ((const int*)ei)[i];
        dd = ((const int*)ei)[Ee + i];
    }
    int pos = atomicAdd(&d_cursor[dd], 1);
    d_colw[pos] = make_int2(s, __float_as_int(d_dis[s] * d_dis[dd]));
}

// ---------------- fp16 tensor-core GEMM (ldmatrix + mma.m16n8k16) -------------
// Y[n,128] = X[n,128] @ W[128,128]; fp16 operands, fp32 accumulate.
// 256 threads = 8 warps, 32r x 32c per warp (4 LDSM per 8 mma):
//   wy = warp & 1  -> rows wy*32..+31 (two m16 tiles)
//   wx = warp >> 1 -> cols wx*32..+31 (four n8 tiles)
#define XPITCH 136
#define WPITCH 136
#define TILE_M 64
#define GEMM_SMEM ((TILE_M * XPITCH + 128 * WPITCH) * 2)

__device__ __forceinline__ void ldm_x4(unsigned& r0, unsigned& r1, unsigned& r2,
                                       unsigned& r3, unsigned addr) {
    asm volatile("ldmatrix.sync.aligned.m8n8.x4.shared.b16 {%0,%1,%2,%3}, [%4];"
                 : "=r"(r0), "=r"(r1), "=r"(r2), "=r"(r3) : "r"(addr));
}
__device__ __forceinline__ void ldm_x4t(unsigned& r0, unsigned& r1, unsigned& r2,
                                        unsigned& r3, unsigned addr) {
    asm volatile("ldmatrix.sync.aligned.m8n8.x4.trans.shared.b16 {%0,%1,%2,%3}, [%4];"
                 : "=r"(r0), "=r"(r1), "=r"(r2), "=r"(r3) : "r"(addr));
}

// stage X tile: fp32 source (layer 1) — convert
__device__ __forceinline__ void stage_X(const float* __restrict__ X, __half* Xs,
                                        int row0, int n, int tid) {
#pragma unroll
    for (int i = 0; i < 8; i++) {
        int idx = i * 256 + tid;
        int r = idx >> 5;
        int c = (idx & 31) * 4;
        float4 xv = make_float4(0.f, 0.f, 0.f, 0.f);
        if (row0 + r < n) xv = *(const float4*)&X[(size_t)(row0 + r) * 128 + c];
        *(uint2*)&Xs[r * XPITCH + c] = f4_to_h4(xv);
    }
}
// stage X tile: fp16 source — straight copy (uint4 = 8 halves)
__device__ __forceinline__ void stage_X(const __half* __restrict__ X, __half* Xs,
                                        int row0, int n, int tid) {
#pragma unroll
    for (int i = 0; i < 4; i++) {
        int idx = i * 256 + tid;
        int r = idx >> 4;
        int c = (idx & 15) * 8;
        uint4 v = make_uint4(0u, 0u, 0u, 0u);
        if (row0 + r < n) v = *(const uint4*)&X[(size_t)(row0 + r) * 128 + c];
        *(uint4*)&Xs[r * XPITCH + c] = v;
    }
}
// stage W (always fp16): 128x128 halves, straight copy
__device__ __forceinline__ void stage_W(const __half* __restrict__ W, __half* Ws, int tid) {
#pragma unroll
    for (int i = 0; i < 8; i++) {
        int idx = i * 256 + tid;
        int r = idx >> 4;
        int c = (idx & 15) * 8;
        *(uint4*)&Ws[r * WPITCH + c] = *(const uint4*)&W[r * 128 + c];
    }
}

// acc[mt][nt][4]: mt in {0,1} (m16 tiles at m0, m0+16), nt in 0..3 (n8 tiles)
#define FP16_GEMM_CORE()                                                          \
    extern __shared__ __align__(16) char smem_raw[];                              \
    __half* Xs = (__half*)smem_raw;                                               \
    __half* Ws = Xs + TILE_M * XPITCH;                                            \
    const int tid = threadIdx.x;                                                  \
    const int row0 = blockIdx.x * TILE_M;                                         \
    stage_W(W, Ws, tid);                                                          \
    stage_X(X, Xs, row0, n, tid);                                                 \
    __syncthreads();                                                              \
    const int warp = tid >> 5;                                                    \
    const int lane = tid & 31;                                                    \
    const int qr = lane >> 2;                                                     \
    const int qc = lane & 3;                                                      \
    const int wy = warp & 1;                                                      \
    const int wx = warp >> 1;                                                     \
    const int m0 = wy * 32;                                                       \
    const int n0 = wx * 32;                                                       \
    const int trow = lane & 7;                                                    \
    const int tsel = lane >> 3;                                                   \
    unsigned xs_b = (unsigned)__cvta_generic_to_shared(Xs);                       \
    unsigned ws_b = (unsigned)__cvta_generic_to_shared(Ws);                       \
    unsigned a_addr0 = xs_b +                                                     \
        ((m0 + trow + 8 * (tsel & 1)) * XPITCH + 8 * (tsel >> 1)) * 2;            \
    unsigned a_addr1 = a_addr0 + 16 * XPITCH * 2;                                 \
    unsigned b_addr = ws_b +                                                      \
        ((trow + 8 * (tsel & 1)) * WPITCH + n0 + 8 * (tsel >> 1)) * 2;            \
    float acc[2][4][4];                                                           \
    _Pragma("unroll")                                                             \
    for (int mt = 0; mt < 2; mt++)                                                \
        _Pragma("unroll")                                                         \
        for (int nt = 0; nt < 4; nt++) {                                          \
            acc[mt][nt][0] = 0.f; acc[mt][nt][1] = 0.f;                           \
            acc[mt][nt][2] = 0.f; acc[mt][nt][3] = 0.f;                           \
        }                                                                         \
    _Pragma("unroll")                                                             \
    for (int ks = 0; ks < 8; ks++) {                                              \
        unsigned a0, a1, a2, a3, c0, c1, c2, c3;                                  \
        ldm_x4(a0, a1, a2, a3, a_addr0 + ks * 32);                                \
        ldm_x4(c0, c1, c2, c3, a_addr1 + ks * 32);                                \
        _Pragma("unroll")                                                         \
        for (int tp = 0; tp < 2; tp++) {                                          \
            unsigned b0, b1, b2, b3;                                              \
            ldm_x4t(b0, b1, b2, b3, b_addr + ks * (16 * WPITCH * 2) + tp * 32);   \
            asm volatile(                                                         \
                "mma.sync.aligned.m16n8k16.row.col.f32.f16.f16.f32 "              \
                "{%0,%1,%2,%3}, {%4,%5,%6,%7}, {%8,%9}, {%0,%1,%2,%3};"           \
                : "+f"(acc[0][2 * tp][0]), "+f"(acc[0][2 * tp][1]),               \
                  "+f"(acc[0][2 * tp][2]), "+f"(acc[0][2 * tp][3])                \
                : "r"(a0), "r"(a1), "r"(a2), "r"(a3), "r"(b0), "r"(b1));          \
            asm volatile(                                                         \
                "mma.sync.aligned.m16n8k16.row.col.f32.f16.f16.f32 "              \
                "{%0,%1,%2,%3}, {%4,%5,%6,%7}, {%8,%9}, {%0,%1,%2,%3};"           \
                : "+f"(acc[0][2 * tp + 1][0]), "+f"(acc[0][2 * tp + 1][1]),       \
                  "+f"(acc[0][2 * tp + 1][2]), "+f"(acc[0][2 * tp + 1][3])        \
                : "r"(a0), "r"(a1), "r"(a2), "r"(a3), "r"(b2), "r"(b3));          \
            asm volatile(                                                         \
                "mma.sync.aligned.m16n8k16.row.col.f32.f16.f16.f32 "              \
                "{%0,%1,%2,%3}, {%4,%5,%6,%7}, {%8,%9}, {%0,%1,%2,%3};"           \
                : "+f"(acc[1][2 * tp][0]), "+f"(acc[1][2 * tp][1]),               \
                  "+f"(acc[1][2 * tp][2]), "+f"(acc[1][2 * tp][3])                \
                : "r"(c0), "r"(c1), "r"(c2), "r"(c3), "r"(b0), "r"(b1));          \
            asm volatile(                                                         \
                "mma.sync.aligned.m16n8k16.row.col.f32.f16.f16.f32 "              \
                "{%0,%1,%2,%3}, {%4,%5,%6,%7}, {%8,%9}, {%0,%1,%2,%3};"           \
                : "+f"(acc[1][2 * tp + 1][0]), "+f"(acc[1][2 * tp + 1][1]),       \
                  "+f"(acc[1][2 * tp + 1][2]), "+f"(acc[1][2 * tp + 1][3])        \
                : "r"(c0), "r"(c1), "r"(c2), "r"(c3), "r"(b2), "r"(b3));          \
        }                                                                         \
    }

// fp16-output GEMM (feeds edge gather); input fp32 or fp16
template <typename TIn>
__global__ __launch_bounds__(256) void gemm_fp16_half_kernel(
    const TIn* __restrict__ X, const __half* __restrict__ W,
    __half* __restrict__ Y, int n) {
    FP16_GEMM_CORE()
#pragma unroll
    for (int mt = 0; mt < 2; mt++) {
        int r_lo = row0 + m0 + mt * 16 + qr;
        int r_hi = r_lo + 8;
        if (r_lo < n) {
#pragma unroll
            for (int nt = 0; nt < 4; nt++)
                *(__half2*)&Y[(size_t)r_lo * 128 + n0 + nt * 8 + qc * 2] =
                    __floats2half2_rn(acc[mt][nt][0], acc[mt][nt][1]);
        }
        if (r_hi < n) {
#pragma unroll
            for (int nt = 0; nt < 4; nt++)
                *(__half2*)&Y[(size_t)r_hi * 128 + n0 + nt * 8 + qc * 2] =
                    __floats2half2_rn(acc[mt][nt][2], acc[mt][nt][3]);
        }
    }
}

// final GEMM with fused predictor head + safe state cleanup (fp16 input).
__global__ __launch_bounds__(256) void gemm_fp16_head_kernel(
    const __half* __restrict__ X, const __half* __restrict__ W,
    const float* __restrict__ bp1, const float* __restrict__ Wp2,
    const float* __restrict__ bp2, float* __restrict__ out, int n) {
    FP16_GEMM_CORE()
    // per-thread partial: p[mt][0] = rows m0+mt*16+qr, p[mt][1] = +8
    float p[2][2];
    p[0][0] = p[0][1] = p[1][0] = p[1][1] = 0.f;
#pragma unroll
    for (int mt = 0; mt < 2; mt++) {
#pragma unroll
        for (int nt = 0; nt < 4; nt++) {
            int c = n0 + nt * 8 + qc * 2;
            float b0v = bp1[c], b1v = bp1[c + 1];
            float w0v = Wp2[c], w1v = Wp2[c + 1];
            p[mt][0] += fmaxf(acc[mt][nt][0] + b0v, 0.f) * w0v +
                        fmaxf(acc[mt][nt][1] + b1v, 0.f) * w1v;
            p[mt][1] += fmaxf(acc[mt][nt][2] + b0v, 0.f) * w0v +
                        fmaxf(acc[mt][nt][3] + b1v, 0.f) * w1v;
        }
        // reduce over the 4 lanes of each row quad
        p[mt][0] += __shfl_xor_sync(0xffffffffu, p[mt][0], 1);
        p[mt][0] += __shfl_xor_sync(0xffffffffu, p[mt][0], 2);
        p[mt][1] += __shfl_xor_sync(0xffffffffu, p[mt][1], 1);
        p[mt][1] += __shfl_xor_sync(0xffffffffu, p[mt][1], 2);
    }
    __syncthreads();
    float* s_head = (float*)smem_raw;  // 64 rows x 4 col-groups
    if (qc == 0) {
#pragma unroll
        for (int mt = 0; mt < 2; mt++) {
            s_head[(m0 + mt * 16 + qr) * 4 + wx]     = p[mt][0];
            s_head[(m0 + mt * 16 + qr + 8) * 4 + wx] = p[mt][1];
        }
    }
    __syncthreads();
    if (tid < TILE_M) {
        int gr = row0 + tid;
        if (gr < n) {
            float z = s_head[tid * 4] + s_head[tid * 4 + 1] +
                      s_head[tid * 4 + 2] + s_head[tid * 4 + 3] + bp2[0];
            out[gr] = 1.f / (1.f + expf(-z));
        }
    }
    // ---- safe cleanup (this kernel never reads these) ----
    int gt = blockIdx.x * 256 + tid;
    if (gt < Nn) d_deg[gt] = 0;
    if (gt < NB_SCAN) d_scan_state[gt] = 0ull;
    if (gt == 0) d_ticket = 0u;
}

// ---------------- CSR aggregation + fused per-graph sum/sumsq -----------------
// A stored fp16 (rounded at store); gsum/gsq accumulated from fp32 values.
__global__ void agg_kernel(const __half* __restrict__ T, const float* __restrict__ bias,
                           __half* __restrict__ A,
                           float* __restrict__ gsum, float* __restrict__ gsq) {
    __shared__ __align__(16) float s_red[2][8][132];
    __shared__ int s_same, s_g;
    int tid = threadIdx.x;
    int wid = tid >> 5;
    int lane = tid & 31;
    int node = blockIdx.x * 8 + wid;
    if (tid == 0) {
        int g0 = d_batch[blockIdx.x * 8];
        int g7 = d_batch[blockIdx.x * 8 + 7];
        s_same = (g0 == g7);
        s_g = g0;
    }
    int s = d_rowptr[node], e = d_rowptr[node + 1];
    float ax = 0.f, ay = 0.f, az = 0.f, aw = 0.f;
    int p = s;
    for (; p + 4 <= e; p += 4) {
        int2 e0 = d_colw[p], e1 = d_colw[p + 1], e2 = d_colw[p + 2], e3 = d_colw[p + 3];
        float w0 = __int_as_float(e0.y), w1 = __int_as_float(e1.y);
        float w2 = __int_as_float(e2.y), w3 = __int_as_float(e3.y);
        uint2 u0 = ((const uint2*)(T + (size_t)e0.x * 128))[lane];
        uint2 u1 = ((const uint2*)(T + (size_t)e1.x * 128))[lane];
        uint2 u2 = ((const uint2*)(T + (size_t)e2.x * 128))[lane];
        uint2 u3 = ((const uint2*)(T + (size_t)e3.x * 128))[lane];
        float2 a0 = __half22float2(*(__half2*)&u0.x), b0 = __half22float2(*(__half2*)&u0.y);
        float2 a1 = __half22float2(*(__half2*)&u1.x), b1 = __half22float2(*(__half2*)&u1.y);
        float2 a2 = __half22float2(*(__half2*)&u2.x), b2 = __half22float2(*(__half2*)&u2.y);
        float2 a3 = __half22float2(*(__half2*)&u3.x), b3 = __half22float2(*(__half2*)&u3.y);
        ax += w0 * a0.x + w1 * a1.x + w2 * a2.x + w3 * a3.x;
        ay += w0 * a0.y + w1 * a1.y + w2 * a2.y + w3 * a3.y;
        az += w0 * b0.x + w1 * b1.x + w2 * b2.x + w3 * b3.x;
        aw += w0 * b0.y + w1 * b1.y + w2 * b2.y + w3 * b3.y;
    }
    for (; p < e; p++) {
        int2 ec = d_colw[p];
        float w = __int_as_float(ec.y);
        uint2 u = ((const uint2*)(T + (size_t)ec.x * 128))[lane];
        float2 a = __half22float2(*(__half2*)&u.x), b = __half22float2(*(__half2*)&u.y);
        ax += w * a.x; ay += w * a.y; az += w * b.x; aw += w * b.y;
    }
    float ds = d_dis[node];
    float sl = ds * ds;
    uint2 ut = ((const uint2*)(T + (size_t)node * 128))[lane];
    float2 ta = __half22float2(*(__half2*)&ut.x), tb = __half22float2(*(__half2*)&ut.y);
    float4 bb = *(const float4*)&bias[lane * 4];
    float4 o;
    o.x = ax + sl * ta.x + bb.x;
    o.y = ay + sl * ta.y + bb.y;
    o.z = az + sl * tb.x + bb.z;
    o.w = aw + sl * tb.y + bb.w;
    ((uint2*)(A + (size_t)node * 128))[lane] = f4_to_h4(o);

    *(float4*)&s_red[0][wid][lane * 4] = o;
    float4 o2 = make_float4(o.x * o.x, o.y * o.y, o.z * o.z, o.w * o.w);
    *(float4*)&s_red[1][wid][lane * 4] = o2;
    __syncthreads();
    if (s_same) {
        if (tid < 128) {
            float t1 = 0.f, t2 = 0.f;
#pragma unroll
            for (int k = 0; k < 8; k++) { t1 += s_red[0][k][tid]; t2 += s_red[1][k][tid]; }
            atomicAdd(&gsum[s_g * 128 + tid], t1);
            atomicAdd(&gsq[s_g * 128 + tid], t2);
        }
    } else {
        int g = d_batch[node];
        atomicAdd(&gsum[g * 128 + lane * 4 + 0], o.x);
        atomicAdd(&gsum[g * 128 + lane * 4 + 1], o.y);
        atomicAdd(&gsum[g * 128 + lane * 4 + 2], o.z);
        atomicAdd(&gsum[g * 128 + lane * 4 + 3], o.w);
        atomicAdd(&gsq[g * 128 + lane * 4 + 0], o2.x);
        atomicAdd(&gsq[g * 128 + lane * 4 + 1], o2.y);
        atomicAdd(&gsq[g * 128 + lane * 4 + 2], o2.z);
        atomicAdd(&gsq[g * 128 + lane * 4 + 3], o2.w);
    }
}

// out(fp16) = [in(fp16) +] relu((A(fp16) - alpha*mean)*rsqrt(var+eps)*gamma + beta)
template <int RES>
__global__ void final_kernel(const __half* __restrict__ A, const __half* __restrict__ in,
                             const float* __restrict__ alpha, const float* __restrict__ gamma,
                             const float* __restrict__ beta, __half* __restrict__ out,
                             const float* __restrict__ gsum, const float* __restrict__ gsq) {
    int idx = blockIdx.x * blockDim.x + threadIdx.x;  // over N*32 groups of 4
    if (idx >= Nn * 32) return;
    int node = idx >> 5;
    int q = idx & 31;
    int g = d_batch[node];
    float inv = 1.f / d_gcntf[g];
    float4 a  = h4_to_f4(((const uint2*)A)[idx]);
    float4 gs = *(const float4*)&gsum[g * 128 + q * 4];
    float4 gq = *(const float4*)&gsq[g * 128 + q * 4];
    float4 al = *(const float4*)&alpha[q * 4];
    float4 ga = *(const float4*)&gamma[q * 4];
    float4 be = *(const float4*)&beta[q * 4];
    float4 m, vv, o;
    m.x = gs.x * inv; m.y = gs.y * inv; m.z = gs.z * inv; m.w = gs.w * inv;
    vv.x = gq.x * inv - m.x * m.x * al.x * (2.f - al.x);
    vv.y = gq.y * inv - m.y * m.y * al.y * (2.f - al.y);
    vv.z = gq.z * inv - m.z * m.z * al.z * (2.f - al.z);
    vv.w = gq.w * inv - m.w * m.w * al.w * (2.f - al.w);
    o.x = fmaxf((a.x - al.x * m.x) * rsqrtf(vv.x + EPSc) * ga.x + be.x, 0.f);
    o.y = fmaxf((a.y - al.y * m.y) * rsqrtf(vv.y + EPSc) * ga.y + be.y, 0.f);
    o.z = fmaxf((a.z - al.z * m.z) * rsqrtf(vv.z + EPSc) * ga.z + be.z, 0.f);
    o.w = fmaxf((a.w - al.w * m.w) * rsqrtf(vv.w + EPSc) * ga.w + be.w, 0.f);
    if (RES) {
        uint2 r = ((const uint2*)in)[idx];
        float2 r0 = __half22float2(*(__half2*)&r.x);
        float2 r1 = __half22float2(*(__half2*)&r.y);
        o.x += r0.x; o.y += r0.y; o.z += r1.x; o.w += r1.y;
    }
    ((uint2*)out)[idx] = f4_to_h4(o);
}

// ---------------- host orchestration ----------------
extern "C" void kernel_launch(void* const* d_in, const int* in_sizes, int n_in,
                              void* d_out, int out_size) {
    const float* x   = (const float*)d_in[0];
    const void*  ei  = d_in[1];
    const void*  bt  = d_in[2];
    const float* W1  = (const float*)d_in[3];
    const float* b1  = (const float*)d_in[4];
    const float* a1  = (const float*)d_in[5];
    const float* g1  = (const float*)d_in[6];
    const float* be1 = (const float*)d_in[7];
    const float* Wm  = (const float*)d_in[8];
    const float* bm  = (const float*)d_in[9];
    const float* am  = (const float*)d_in[10];
    const float* gm  = (const float*)d_in[11];
    const float* bem = (const float*)d_in[12];
    const float* WL  = (const float*)d_in[13];
    const float* bL  = (const float*)d_in[14];
    const float* aL  = (const float*)d_in[15];
    const float* gL  = (const float*)d_in[16];
    const float* beL = (const float*)d_in[17];
    const float* Wp1 = (const float*)d_in[18];
    const float* bp1 = (const float*)d_in[19];
    const float* Wp2 = (const float*)d_in[20];
    const float* bp2 = (const float*)d_in[21];
    float* out = (float*)d_out;

    float *GS, *GQ;
    __half *HAh, *HBh, *Th, *Ah, *Wh;
    cudaGetSymbolAddress((void**)&HAh, d_HAh);
    cudaGetSymbolAddress((void**)&HBh, d_HBh);
    cudaGetSymbolAddress((void**)&Th,  d_Th);
    cudaGetSymbolAddress((void**)&Ah,  d_Ah);
    cudaGetSymbolAddress((void**)&GS,  d_gsum);
    cudaGetSymbolAddress((void**)&GQ,  d_gsq);
    cudaGetSymbolAddress((void**)&Wh,  d_Wh);

    // side stream + fork/join events (created once, on the correctness call;
    // streams/events are not device-memory allocations)
    static cudaStream_t s1 = nullptr;
    static cudaEvent_t evF = nullptr, evJ = nullptr;
    if (s1 == nullptr) {
        cudaStreamCreateWithFlags(&s1, cudaStreamNonBlocking);
        cudaEventCreateWithFlags(&evF, cudaEventDisableTiming);
        cudaEventCreateWithFlags(&evJ, cudaEventDisableTiming);
    }

    const int smem = GEMM_SMEM;
    cudaFuncSetAttribute(gemm_fp16_half_kernel<float>,  cudaFuncAttributeMaxDynamicSharedMemorySize, smem);
    cudaFuncSetAttribute(gemm_fp16_half_kernel<__half>, cudaFuncAttributeMaxDynamicSharedMemorySize, smem);
    cudaFuncSetAttribute(gemm_fp16_head_kernel, cudaFuncAttributeMaxDynamicSharedMemorySize, smem);

    const int gemm_grid = (Nn + TILE_M - 1) / TILE_M;  // 782
    const int agg_grid  = Nn / 8;   // 6250, exact
    const int elem_grid = (Nn * 32 + 511) / 512;
    const int GL = NGg * Hh;
    const int WSZ = Hh * Hh;

    // ---- fork: preprocessing chain on s1, W1-convert + layer-1 GEMM on s0 ----
    cudaEventRecord(evF, 0);
    cudaStreamWaitEvent(s1, evF, 0);

    // s1: CSR construction (independent of GEMM path)
    hist_kernel<<<1024, 256, 0, s1>>>(ei, bt);
    scan_fused_kernel<<<NB_SCAN, 256, 0, s1>>>();
    scatter_kernel<<<(Ee + 255) / 256, 256, 0, s1>>>(ei);  // also zeroes gsum/gsq
    cudaEventRecord(evJ, s1);

    // s0 (default): W1 -> fp16, layer-1 GEMM, then remaining weights
    convert_w1_kernel<<<16, 256>>>(W1);
    gemm_fp16_half_kernel<float><<<gemm_grid, 256, smem>>>(x, Wh + 0 * WSZ, Th, Nn);
    convert_wrest_kernel<<<64, 256>>>(Wm, WL, Wp1);  // done long before layer-2 GEMM

    // join before the first aggregation
    cudaStreamWaitEvent(0, evJ, 0);

    // ---- layer 1 aggregate + norm -> HBh ----
    agg_kernel<<<agg_grid, 256>>>(Th, b1, Ah, GS + 0 * GL, GQ + 0 * GL);
    final_kernel<0><<<elem_grid, 512>>>(Ah, nullptr, a1, g1, be1, HBh, GS + 0 * GL, GQ + 0 * GL);

    // ---- mid layer 0 (residual): HBh -> HAh ----
    gemm_fp16_half_kernel<__half><<<gemm_grid, 256, smem>>>(HBh, Wh + 1 * WSZ, Th, Nn);
    agg_kernel<<<agg_grid, 256>>>(Th, bm + 0 * 128, Ah, GS + 1 * GL, GQ + 1 * GL);
    final_kernel<1><<<elem_grid, 512>>>(Ah, HBh, am + 0 * 128, gm + 0 * 128, bem + 0 * 128, HAh,
                                        GS + 1 * GL, GQ + 1 * GL);

    // ---- mid layer 1 (residual): HAh -> HBh ----
    gemm_fp16_half_kernel<__half><<<gemm_grid, 256, smem>>>(HAh, Wh + 2 * WSZ, Th, Nn);
    agg_kernel<<<agg_grid, 256>>>(Th, bm + 1 * 128, Ah, GS + 2 * GL, GQ + 2 * GL);
    final_kernel<1><<<elem_grid, 512>>>(Ah, HAh, am + 1 * 128, gm + 1 * 128, bem + 1 * 128, HBh,
                                        GS + 2 * GL, GQ + 2 * GL);

    // ---- last layer: HBh -> HAh ----
    gemm_fp16_half_kernel<__half><<<gemm_grid, 256, smem>>>(HBh, Wh + 3 * WSZ, Th, Nn);
    agg_kernel<<<agg_grid, 256>>>(Th, bL, Ah, GS + 3 * GL, GQ + 3 * GL);
    final_kernel<0><<<elem_grid, 512>>>(Ah, nullptr, aL, gL, beL, HAh, GS + 3 * GL, GQ + 3 * GL);

    // ---- predictor: HAh -> out (GEMM + fused head + safe cleanup) ----
    gemm_fp16_head_kernel<<<gemm_grid, 256, smem>>>(HAh, Wh + 4 * WSZ, bp1, Wp2, bp2, out, Nn);
}

// round 17
// speedup vs baseline: 1.1111x; 1.0272x over previous
#include <cuda_runtime.h>
#include <cuda_fp16.h>
#include <math.h>

#define Nn 50000
#define Hh 128
#define Ee 800000
#define NGg 64
#define EPSc 1e-5f
#define NB_SCAN 196   // ceil(50000/256)

// ---------------- device scratch (static globals; no allocation) ----------------
// All mutable state is zero at module load. Cleanup split to avoid races:
//  - d_gsum/d_gsq: zeroed by scatter_kernel (before any agg of the same run).
//  - d_deg/d_scan_state/d_ticket: zeroed by gemm_head epilogue (head never
//    reads them; next run's hist/scan are separate launches).
__device__ int    d_batch[Nn];
__device__ int    d_deg[Nn];
__device__ float  d_dis[Nn];
__device__ int    d_rowptr[Nn + 1];
__device__ int    d_cursor[Nn];
__device__ int2   d_colw[Ee];
__device__ unsigned long long d_scan_state[NB_SCAN];
__device__ unsigned d_ticket;
__device__ int    d_gstart[NGg + 1];
__device__ float  d_gcntf[NGg];
__device__ float  d_gsum[4 * NGg * Hh];
__device__ float  d_gsq[4 * NGg * Hh];
__device__ __half d_HAh[(size_t)Nn * Hh];   // fp16 hidden state A
__device__ __half d_HBh[(size_t)Nn * Hh];   // fp16 hidden state B
__device__ __half d_Th[(size_t)Nn * Hh];    // fp16 GEMM output (gather source)
__device__ __half d_Ah[(size_t)Nn * Hh];    // fp16 aggregated pre-norm
__device__ __half d_Wh[5 * Hh * Hh];        // fp16 weights: W1,Wm0,Wm1,WL,Wp1

__device__ __forceinline__ uint2 f4_to_h4(float4 v) {
    uint2 o;
    *(__half2*)&o.x = __floats2half2_rn(v.x, v.y);
    *(__half2*)&o.y = __floats2half2_rn(v.z, v.w);
    return o;
}
__device__ __forceinline__ float4 h4_to_f4(uint2 u) {
    float2 a = __half22float2(*(__half2*)&u.x);
    float2 b = __half22float2(*(__half2*)&u.y);
    return make_float4(a.x, a.y, b.x, b.y);
}

// ---------------- dtype detection (per-block, no global state) ----------------
__device__ __forceinline__ int detect_is64(const void* ei) {
    const long long* p = (const long long*)ei;
    int ok = 1;
#pragma unroll
    for (int k = 0; k < 16; k++) {
        long long v = p[k];
        if (v < 0 || v >= (long long)Nn) ok = 0;
    }
    return ok;
}

// ---------------- preprocessing ----------------

// convert ONLY W1 to fp16 (critical path before gemm_l1): 16 blocks
__global__ void convert_w1_kernel(const float* __restrict__ W1) {
    int i = blockIdx.x * blockDim.x + threadIdx.x;  // over 4096 float4 groups
    if (i >= 4096) return;
    ((uint2*)d_Wh)[i] = f4_to_h4(((const float4*)W1)[i]);
}

// convert the remaining 4 weight matrices (off the critical path)
__global__ void convert_wrest_kernel(const float* __restrict__ Wm,
                                     const float* __restrict__ WL,
                                     const float* __restrict__ Wp1) {
    int i = blockIdx.x * blockDim.x + threadIdx.x;  // over 4*4096 float4 groups
    if (i >= 4 * 4096) return;
    int m = i >> 12;
    int j = i & 4095;
    const float* src;
    switch (m) {
        case 0: src = Wm; break;
        case 1: src = Wm + 16384; break;
        case 2: src = WL; break;
        default: src = Wp1; break;
    }
    ((uint2*)d_Wh)[4096 + i] = f4_to_h4(((const float4*)src)[j]);
}

// batch convert + dst-degree histogram (stream 1)
__global__ void hist_kernel(const void* ei, const void* bt) {
    __shared__ int s_is64;
    if (threadIdx.x == 0) s_is64 = detect_is64(ei);
    __syncthreads();
    int is64 = s_is64;
    int gtid = blockIdx.x * blockDim.x + threadIdx.x;
    int stride = gridDim.x * blockDim.x;
    for (int i = gtid; i < Ee; i += stride) {
        int v = is64 ? (int)((const long long*)ei)[Ee + i] : ((const int*)ei)[Ee + i];
        atomicAdd(&d_deg[v], 1);
    }
    for (int i = gtid; i < Nn; i += stride) {
        int v = is64 ? (int)((const long long*)bt)[i] : ((const int*)bt)[i];
        d_batch[i] = v;
    }
}

// decoupled-lookback scan of d_deg -> rowptr/cursor/dis + per-graph ranges
__global__ void scan_fused_kernel() {
    __shared__ unsigned sbid;
    __shared__ int s_excl;
    __shared__ int sh[256];
    if (threadIdx.x == 0) sbid = atomicAdd(&d_ticket, 1u);
    __syncthreads();
    int b = (int)sbid;
    int idx = b * 256 + threadIdx.x;
    int deg = (idx < Nn) ? d_deg[idx] : 0;
    sh[threadIdx.x] = deg;
    __syncthreads();
    for (int off = 1; off < 256; off <<= 1) {
        int u = 0;
        if (threadIdx.x >= off) u = sh[threadIdx.x - off];
        __syncthreads();
        if (threadIdx.x >= off) sh[threadIdx.x] += u;
        __syncthreads();
    }
    int incl = sh[threadIdx.x];
    int aggr = sh[255];
    if (threadIdx.x == 0) {
        if (b == 0) {
            atomicExch(&d_scan_state[0], (2ull << 32) | (unsigned)aggr);
            s_excl = 0;
        } else {
            atomicExch(&d_scan_state[b], (1ull << 32) | (unsigned)aggr);
            int excl = 0;
            int j = b - 1;
            while (true) {
                unsigned long long st;
                do { st = atomicAdd(&d_scan_state[j], 0ull); } while ((st >> 32) == 0ull);
                excl += (int)(unsigned)st;
                if ((st >> 32) == 2ull) break;
                j--;
            }
            atomicExch(&d_scan_state[b], (2ull << 32) | (unsigned)(excl + aggr));
            s_excl = excl;
        }
    }
    __syncthreads();
    int excl = s_excl;
    if (idx < Nn) {
        d_rowptr[idx + 1] = excl + incl;
        if (idx == 0) d_rowptr[0] = 0;
        d_cursor[idx] = excl + incl - deg;
        d_dis[idx] = rsqrtf((float)deg + 1.0f);
    }
    if (b == 0) {
        int t = threadIdx.x;
        if (t <= NGg) {
            int lo = 0, hi = Nn;
            while (lo < hi) {
                int mid = (lo + hi) >> 1;
                if (d_batch[mid] < t) lo = mid + 1; else hi = mid;
            }
            d_gstart[t] = lo;
        }
        __syncthreads();
        if (t < NGg) {
            int c = d_gstart[t + 1] - d_gstart[t];
            d_gcntf[t] = (c > 0) ? (float)c : 1.0f;
        }
    }
}

// scatter edges into CSR + zero gsum/gsq accumulators for this run
__global__ void scatter_kernel(const void* ei) {
    __shared__ int s_is64;
    if (threadIdx.x == 0) s_is64 = detect_is64(ei);
    __syncthreads();
    int i = blockIdx.x * blockDim.x + threadIdx.x;
    if (i < 4 * NGg * Hh) { d_gsum[i] = 0.f; d_gsq[i] = 0.f; }
    if (i >= Ee) return;
    int s, dd;
    if (s_is64) {
        s  = (int)((const long long*)ei)[i];
        dd = (int)((const long long*)ei)[Ee + i];
    } else {
        s  = ((const int*)ei)[i];
        dd = ((const int*)ei)[Ee + i];
    }
    int pos = atomicAdd(&d_cursor[dd], 1);
    d_colw[pos] = make_int2(s, __float_as_int(d_dis[s] * d_dis[dd]));
}

// ---------------- fp16 tensor-core GEMM (ldmatrix + mma.m16n8k16) -------------
// Y[n,128] = X[n,128] @ W[128,128]; fp16 operands, fp32 accumulate.
// 256 threads = 8 warps, 32r x 32c per warp (4 LDSM per 8 mma):
//   wy = warp & 1  -> rows wy*32..+31 (two m16 tiles)
//   wx = warp >> 1 -> cols wx*32..+31 (four n8 tiles)
// gemm_fp16_half_kernel is 2-tile persistent: grid 391 = single wave at occ 4;
// W staged once per block, X re-staged per tile.
#define XPITCH 136
#define WPITCH 136
#define TILE_M 64
#define GEMM_SMEM ((TILE_M * XPITCH + 128 * WPITCH) * 2)

__device__ __forceinline__ void ldm_x4(unsigned& r0, unsigned& r1, unsigned& r2,
                                       unsigned& r3, unsigned addr) {
    asm volatile("ldmatrix.sync.aligned.m8n8.x4.shared.b16 {%0,%1,%2,%3}, [%4];"
                 : "=r"(r0), "=r"(r1), "=r"(r2), "=r"(r3) : "r"(addr));
}
__device__ __forceinline__ void ldm_x4t(unsigned& r0, unsigned& r1, unsigned& r2,
                                        unsigned& r3, unsigned addr) {
    asm volatile("ldmatrix.sync.aligned.m8n8.x4.trans.shared.b16 {%0,%1,%2,%3}, [%4];"
                 : "=r"(r0), "=r"(r1), "=r"(r2), "=r"(r3) : "r"(addr));
}

// stage X tile: fp32 source (layer 1) — convert
__device__ __forceinline__ void stage_X(const float* __restrict__ X, __half* Xs,
                                        int row0, int n, int tid) {
#pragma unroll
    for (int i = 0; i < 8; i++) {
        int idx = i * 256 + tid;
        int r = idx >> 5;
        int c = (idx & 31) * 4;
        float4 xv = make_float4(0.f, 0.f, 0.f, 0.f);
        if (row0 + r < n) xv = *(const float4*)&X[(size_t)(row0 + r) * 128 + c];
        *(uint2*)&Xs[r * XPITCH + c] = f4_to_h4(xv);
    }
}
// stage X tile: fp16 source — straight copy (uint4 = 8 halves)
__device__ __forceinline__ void stage_X(const __half* __restrict__ X, __half* Xs,
                                        int row0, int n, int tid) {
#pragma unroll
    for (int i = 0; i < 4; i++) {
        int idx = i * 256 + tid;
        int r = idx >> 4;
        int c = (idx & 15) * 8;
        uint4 v = make_uint4(0u, 0u, 0u, 0u);
        if (row0 + r < n) v = *(const uint4*)&X[(size_t)(row0 + r) * 128 + c];
        *(uint4*)&Xs[r * XPITCH + c] = v;
    }
}
// stage W (always fp16): 128x128 halves, straight copy
__device__ __forceinline__ void stage_W(const __half* __restrict__ W, __half* Ws, int tid) {
#pragma unroll
    for (int i = 0; i < 8; i++) {
        int idx = i * 256 + tid;
        int r = idx >> 4;
        int c = (idx & 15) * 8;
        *(uint4*)&Ws[r * WPITCH + c] = *(const uint4*)&W[r * 128 + c];
    }
}

// per-tile mma: acc[2][4][4] over 8 k16 steps (4 LDSM per 8 mma)
#define GEMM_TILE_MMA()                                                           \
    float acc[2][4][4];                                                           \
    _Pragma("unroll")                                                             \
    for (int mt = 0; mt < 2; mt++)                                                \
        _Pragma("unroll")                                                         \
        for (int nt = 0; nt < 4; nt++) {                                          \
            acc[mt][nt][0] = 0.f; acc[mt][nt][1] = 0.f;                           \
            acc[mt][nt][2] = 0.f; acc[mt][nt][3] = 0.f;                           \
        }                                                                         \
    _Pragma("unroll")                                                             \
    for (int ks = 0; ks < 8; ks++) {                                              \
        unsigned a0, a1, a2, a3, c0, c1, c2, c3;                                  \
        ldm_x4(a0, a1, a2, a3, a_addr0 + ks * 32);                                \
        ldm_x4(c0, c1, c2, c3, a_addr1 + ks * 32);                                \
        _Pragma("unroll")                                                         \
        for (int tp = 0; tp < 2; tp++) {                                          \
            unsigned b0, b1, b2, b3;                                              \
            ldm_x4t(b0, b1, b2, b3, b_addr + ks * (16 * WPITCH * 2) + tp * 32);   \
            asm volatile(                                                         \
                "mma.sync.aligned.m16n8k16.row.col.f32.f16.f16.f32 "              \
                "{%0,%1,%2,%3}, {%4,%5,%6,%7}, {%8,%9}, {%0,%1,%2,%3};"           \
                : "+f"(acc[0][2 * tp][0]), "+f"(acc[0][2 * tp][1]),               \
                  "+f"(acc[0][2 * tp][2]), "+f"(acc[0][2 * tp][3])                \
                : "r"(a0), "r"(a1), "r"(a2), "r"(a3), "r"(b0), "r"(b1));          \
            asm volatile(                                                         \
                "mma.sync.aligned.m16n8k16.row.col.f32.f16.f16.f32 "              \
                "{%0,%1,%2,%3}, {%4,%5,%6,%7}, {%8,%9}, {%0,%1,%2,%3};"           \
                : "+f"(acc[0][2 * tp + 1][0]), "+f"(acc[0][2 * tp + 1][1]),       \
                  "+f"(acc[0][2 * tp + 1][2]), "+f"(acc[0][2 * tp + 1][3])        \
                : "r"(a0), "r"(a1), "r"(a2), "r"(a3), "r"(b2), "r"(b3));          \
            asm volatile(                                                         \
                "mma.sync.aligned.m16n8k16.row.col.f32.f16.f16.f32 "              \
                "{%0,%1,%2,%3}, {%4,%5,%6,%7}, {%8,%9}, {%0,%1,%2,%3};"           \
                : "+f"(acc[1][2 * tp][0]), "+f"(acc[1][2 * tp][1]),               \
                  "+f"(acc[1][2 * tp][2]), "+f"(acc[1][2 * tp][3])                \
                : "r"(c0), "r"(c1), "r"(c2), "r"(c3), "r"(b0), "r"(b1));          \
            asm volatile(                                                         \
                "mma.sync.aligned.m16n8k16.row.col.f32.f16.f16.f32 "              \
                "{%0,%1,%2,%3}, {%4,%5,%6,%7}, {%8,%9}, {%0,%1,%2,%3};"           \
                : "+f"(acc[1][2 * tp + 1][0]), "+f"(acc[1][2 * tp + 1][1]),       \
                  "+f"(acc[1][2 * tp + 1][2]), "+f"(acc[1][2 * tp + 1][3])        \
                : "r"(c0), "r"(c1), "r"(c2), "r"(c3), "r"(b2), "r"(b3));          \
        }                                                                         \
    }

#define GEMM_WARP_SETUP()                                                         \
    const int warp = tid >> 5;                                                    \
    const int lane = tid & 31;                                                    \
    const int qr = lane >> 2;                                                     \
    const int qc = lane & 3;                                                      \
    const int wy = warp & 1;                                                      \
    const int wx = warp >> 1;                                                     \
    const int m0 = wy * 32;                                                       \
    const int n0 = wx * 32;                                                       \
    const int trow = lane & 7;                                                    \
    const int tsel = lane >> 3;                                                   \
    unsigned xs_b = (unsigned)__cvta_generic_to_shared(Xs);                       \
    unsigned ws_b = (unsigned)__cvta_generic_to_shared(Ws);                       \
    unsigned a_addr0 = xs_b +                                                     \
        ((m0 + trow + 8 * (tsel & 1)) * XPITCH + 8 * (tsel >> 1)) * 2;            \
    unsigned a_addr1 = a_addr0 + 16 * XPITCH * 2;                                 \
    unsigned b_addr = ws_b +                                                      \
        ((trow + 8 * (tsel & 1)) * WPITCH + n0 + 8 * (tsel >> 1)) * 2;

// 2-tile persistent fp16-output GEMM; input fp32 or fp16
template <typename TIn>
__global__ __launch_bounds__(256) void gemm_fp16_half_kernel(
    const TIn* __restrict__ X, const __half* __restrict__ W,
    __half* __restrict__ Y, int n) {
    extern __shared__ __align__(16) char smem_raw[];
    __half* Xs = (__half*)smem_raw;
    __half* Ws = Xs + TILE_M * XPITCH;
    const int tid = threadIdx.x;
    stage_W(W, Ws, tid);
    GEMM_WARP_SETUP()
#pragma unroll
    for (int t = 0; t < 2; t++) {
        int row0 = (blockIdx.x + t * gridDim.x) * TILE_M;
        if (row0 >= n) break;
        if (t > 0) __syncthreads();  // prior tile's ldsm reads done before Xs overwrite
        stage_X(X, Xs, row0, n, tid);
        __syncthreads();             // X (and W on t=0) visible
        GEMM_TILE_MMA()
#pragma unroll
        for (int mt = 0; mt < 2; mt++) {
            int r_lo = row0 + m0 + mt * 16 + qr;
            int r_hi = r_lo + 8;
            if (r_lo < n) {
#pragma unroll
                for (int nt = 0; nt < 4; nt++)
                    *(__half2*)&Y[(size_t)r_lo * 128 + n0 + nt * 8 + qc * 2] =
                        __floats2half2_rn(acc[mt][nt][0], acc[mt][nt][1]);
            }
            if (r_hi < n) {
#pragma unroll
                for (int nt = 0; nt < 4; nt++)
                    *(__half2*)&Y[(size_t)r_hi * 128 + n0 + nt * 8 + qc * 2] =
                        __floats2half2_rn(acc[mt][nt][2], acc[mt][nt][3]);
            }
        }
    }
}

// final GEMM with fused predictor head + safe state cleanup (fp16 input).
// Single-tile (grid 782) — head epilogue needs per-tile smem reduction.
__global__ __launch_bounds__(256) void gemm_fp16_head_kernel(
    const __half* __restrict__ X, const __half* __restrict__ W,
    const float* __restrict__ bp1, const float* __restrict__ Wp2,
    const float* __restrict__ bp2, float* __restrict__ out, int n) {
    extern __shared__ __align__(16) char smem_raw[];
    __half* Xs = (__half*)smem_raw;
    __half* Ws = Xs + TILE_M * XPITCH;
    const int tid = threadIdx.x;
    const int row0 = blockIdx.x * TILE_M;
    stage_W(W, Ws, tid);
    stage_X(X, Xs, row0, n, tid);
    __syncthreads();
    GEMM_WARP_SETUP()
    GEMM_TILE_MMA()
    // per-thread partial: p[mt][0] = rows m0+mt*16+qr, p[mt][1] = +8
    float p[2][2];
    p[0][0] = p[0][1] = p[1][0] = p[1][1] = 0.f;
#pragma unroll
    for (int mt = 0; mt < 2; mt++) {
#pragma unroll
        for (int nt = 0; nt < 4; nt++) {
            int c = n0 + nt * 8 + qc * 2;
            float b0v = bp1[c], b1v = bp1[c + 1];
            float w0v = Wp2[c], w1v = Wp2[c + 1];
            p[mt][0] += fmaxf(acc[mt][nt][0] + b0v, 0.f) * w0v +
                        fmaxf(acc[mt][nt][1] + b1v, 0.f) * w1v;
            p[mt][1] += fmaxf(acc[mt][nt][2] + b0v, 0.f) * w0v +
                        fmaxf(acc[mt][nt][3] + b1v, 0.f) * w1v;
        }
        p[mt][0] += __shfl_xor_sync(0xffffffffu, p[mt][0], 1);
        p[mt][0] += __shfl_xor_sync(0xffffffffu, p[mt][0], 2);
        p[mt][1] += __shfl_xor_sync(0xffffffffu, p[mt][1], 1);
        p[mt][1] += __shfl_xor_sync(0xffffffffu, p[mt][1], 2);
    }
    __syncthreads();
    float* s_head = (float*)smem_raw;  // 64 rows x 4 col-groups
    if (qc == 0) {
#pragma unroll
        for (int mt = 0; mt < 2; mt++) {
            s_head[(m0 + mt * 16 + qr) * 4 + wx]     = p[mt][0];
            s_head[(m0 + mt * 16 + qr + 8) * 4 + wx] = p[mt][1];
        }
    }
    __syncthreads();
    if (tid < TILE_M) {
        int gr = row0 + tid;
        if (gr < n) {
            float z = s_head[tid * 4] + s_head[tid * 4 + 1] +
                      s_head[tid * 4 + 2] + s_head[tid * 4 + 3] + bp2[0];
            out[gr] = 1.f / (1.f + expf(-z));
        }
    }
    // ---- safe cleanup (this kernel never reads these) ----
    int gt = blockIdx.x * 256 + tid;
    if (gt < Nn) d_deg[gt] = 0;
    if (gt < NB_SCAN) d_scan_state[gt] = 0ull;
    if (gt == 0) d_ticket = 0u;
}

// ---------------- CSR aggregation + fused per-graph sum/sumsq -----------------
// A stored fp16 (rounded at store); gsum/gsq accumulated from fp32 values.
__global__ void agg_kernel(const __half* __restrict__ T, const float* __restrict__ bias,
                           __half* __restrict__ A,
                           float* __restrict__ gsum, float* __restrict__ gsq) {
    __shared__ __align__(16) float s_red[2][8][132];
    __shared__ int s_same, s_g;
    int tid = threadIdx.x;
    int wid = tid >> 5;
    int lane = tid & 31;
    int node = blockIdx.x * 8 + wid;
    if (tid == 0) {
        int g0 = d_batch[blockIdx.x * 8];
        int g7 = d_batch[blockIdx.x * 8 + 7];
        s_same = (g0 == g7);
        s_g = g0;
    }
    int s = d_rowptr[node], e = d_rowptr[node + 1];
    float ax = 0.f, ay = 0.f, az = 0.f, aw = 0.f;
    int p = s;
    for (; p + 4 <= e; p += 4) {
        int2 e0 = d_colw[p], e1 = d_colw[p + 1], e2 = d_colw[p + 2], e3 = d_colw[p + 3];
        float w0 = __int_as_float(e0.y), w1 = __int_as_float(e1.y);
        float w2 = __int_as_float(e2.y), w3 = __int_as_float(e3.y);
        uint2 u0 = ((const uint2*)(T + (size_t)e0.x * 128))[lane];
        uint2 u1 = ((const uint2*)(T + (size_t)e1.x * 128))[lane];
        uint2 u2 = ((const uint2*)(T + (size_t)e2.x * 128))[lane];
        uint2 u3 = ((const uint2*)(T + (size_t)e3.x * 128))[lane];
        float2 a0 = __half22float2(*(__half2*)&u0.x), b0 = __half22float2(*(__half2*)&u0.y);
        float2 a1 = __half22float2(*(__half2*)&u1.x), b1 = __half22float2(*(__half2*)&u1.y);
        float2 a2 = __half22float2(*(__half2*)&u2.x), b2 = __half22float2(*(__half2*)&u2.y);
        float2 a3 = __half22float2(*(__half2*)&u3.x), b3 = __half22float2(*(__half2*)&u3.y);
        ax += w0 * a0.x + w1 * a1.x + w2 * a2.x + w3 * a3.x;
        ay += w0 * a0.y + w1 * a1.y + w2 * a2.y + w3 * a3.y;
        az += w0 * b0.x + w1 * b1.x + w2 * b2.x + w3 * b3.x;
        aw += w0 * b0.y + w1 * b1.y + w2 * b2.y + w3 * b3.y;
    }
    for (; p < e; p++) {
        int2 ec = d_colw[p];
        float w = __int_as_float(ec.y);
        uint2 u = ((const uint2*)(T + (size_t)ec.x * 128))[lane];
        float2 a = __half22float2(*(__half2*)&u.x), b = __half22float2(*(__half2*)&u.y);
        ax += w * a.x; ay += w * a.y; az += w * b.x; aw += w * b.y;
    }
    float ds = d_dis[node];
    float sl = ds * ds;
    uint2 ut = ((const uint2*)(T + (size_t)node * 128))[lane];
    float2 ta = __half22float2(*(__half2*)&ut.x), tb = __half22float2(*(__half2*)&ut.y);
    float4 bb = *(const float4*)&bias[lane * 4];
    float4 o;
    o.x = ax + sl * ta.x + bb.x;
    o.y = ay + sl * ta.y + bb.y;
    o.z = az + sl * tb.x + bb.z;
    o.w = aw + sl * tb.y + bb.w;
    ((uint2*)(A + (size_t)node * 128))[lane] = f4_to_h4(o);

    *(float4*)&s_red[0][wid][lane * 4] = o;
    float4 o2 = make_float4(o.x * o.x, o.y * o.y, o.z * o.z, o.w * o.w);
    *(float4*)&s_red[1][wid][lane * 4] = o2;
    __syncthreads();
    if (s_same) {
        if (tid < 128) {
            float t1 = 0.f, t2 = 0.f;
#pragma unroll
            for (int k = 0; k < 8; k++) { t1 += s_red[0][k][tid]; t2 += s_red[1][k][tid]; }
            atomicAdd(&gsum[s_g * 128 + tid], t1);
            atomicAdd(&gsq[s_g * 128 + tid], t2);
        }
    } else {
        int g = d_batch[node];
        atomicAdd(&gsum[g * 128 + lane * 4 + 0], o.x);
        atomicAdd(&gsum[g * 128 + lane * 4 + 1], o.y);
        atomicAdd(&gsum[g * 128 + lane * 4 + 2], o.z);
        atomicAdd(&gsum[g * 128 + lane * 4 + 3], o.w);
        atomicAdd(&gsq[g * 128 + lane * 4 + 0], o2.x);
        atomicAdd(&gsq[g * 128 + lane * 4 + 1], o2.y);
        atomicAdd(&gsq[g * 128 + lane * 4 + 2], o2.z);
        atomicAdd(&gsq[g * 128 + lane * 4 + 3], o2.w);
    }
}

// out(fp16) = [in(fp16) +] relu((A(fp16) - alpha*mean)*rsqrt(var+eps)*gamma + beta)
template <int RES>
__global__ void final_kernel(const __half* __restrict__ A, const __half* __restrict__ in,
                             const float* __restrict__ alpha, const float* __restrict__ gamma,
                             const float* __restrict__ beta, __half* __restrict__ out,
                             const float* __restrict__ gsum, const float* __restrict__ gsq) {
    int idx = blockIdx.x * blockDim.x + threadIdx.x;  // over N*32 groups of 4
    if (idx >= Nn * 32) return;
    int node = idx >> 5;
    int q = idx & 31;
    int g = d_batch[node];
    float inv = 1.f / d_gcntf[g];
    float4 a  = h4_to_f4(((const uint2*)A)[idx]);
    float4 gs = *(const float4*)&gsum[g * 128 + q * 4];
    float4 gq = *(const float4*)&gsq[g * 128 + q * 4];
    float4 al = *(const float4*)&alpha[q * 4];
    float4 ga = *(const float4*)&gamma[q * 4];
    float4 be = *(const float4*)&beta[q * 4];
    float4 m, vv, o;
    m.x = gs.x * inv; m.y = gs.y * inv; m.z = gs.z * inv; m.w = gs.w * inv;
    vv.x = gq.x * inv - m.x * m.x * al.x * (2.f - al.x);
    vv.y = gq.y * inv - m.y * m.y * al.y * (2.f - al.y);
    vv.z = gq.z * inv - m.z * m.z * al.z * (2.f - al.z);
    vv.w = gq.w * inv - m.w * m.w * al.w * (2.f - al.w);
    o.x = fmaxf((a.x - al.x * m.x) * rsqrtf(vv.x + EPSc) * ga.x + be.x, 0.f);
    o.y = fmaxf((a.y - al.y * m.y) * rsqrtf(vv.y + EPSc) * ga.y + be.y, 0.f);
    o.z = fmaxf((a.z - al.z * m.z) * rsqrtf(vv.z + EPSc) * ga.z + be.z, 0.f);
    o.w = fmaxf((a.w - al.w * m.w) * rsqrtf(vv.w + EPSc) * ga.w + be.w, 0.f);
    if (RES) {
        uint2 r = ((const uint2*)in)[idx];
        float2 r0 = __half22float2(*(__half2*)&r.x);
        float2 r1 = __half22float2(*(__half2*)&r.y);
        o.x += r0.x; o.y += r0.y; o.z += r1.x; o.w += r1.y;
    }
    ((uint2*)out)[idx] = f4_to_h4(o);
}

// ---------------- host orchestration ----------------
extern "C" void kernel_launch(void* const* d_in, const int* in_sizes, int n_in,
                              void* d_out, int out_size) {
    const float* x   = (const float*)d_in[0];
    const void*  ei  = d_in[1];
    const void*  bt  = d_in[2];
    const float* W1  = (const float*)d_in[3];
    const float* b1  = (const float*)d_in[4];
    const float* a1  = (const float*)d_in[5];
    const float* g1  = (const float*)d_in[6];
    const float* be1 = (const float*)d_in[7];
    const float* Wm  = (const float*)d_in[8];
    const float* bm  = (const float*)d_in[9];
    const float* am  = (const float*)d_in[10];
    const float* gm  = (const float*)d_in[11];
    const float* bem = (const float*)d_in[12];
    const float* WL  = (const float*)d_in[13];
    const float* bL  = (const float*)d_in[14];
    const float* aL  = (const float*)d_in[15];
    const float* gL  = (const float*)d_in[16];
    const float* beL = (const float*)d_in[17];
    const float* Wp1 = (const float*)d_in[18];
    const float* bp1 = (const float*)d_in[19];
    const float* Wp2 = (const float*)d_in[20];
    const float* bp2 = (const float*)d_in[21];
    float* out = (float*)d_out;

    float *GS, *GQ;
    __half *HAh, *HBh, *Th, *Ah, *Wh;
    cudaGetSymbolAddress((void**)&HAh, d_HAh);
    cudaGetSymbolAddress((void**)&HBh, d_HBh);
    cudaGetSymbolAddress((void**)&Th,  d_Th);
    cudaGetSymbolAddress((void**)&Ah,  d_Ah);
    cudaGetSymbolAddress((void**)&GS,  d_gsum);
    cudaGetSymbolAddress((void**)&GQ,  d_gsq);
    cudaGetSymbolAddress((void**)&Wh,  d_Wh);

    // side stream + fork/join events (created once, on the correctness call;
    // streams/events are not device-memory allocations)
    static cudaStream_t s1 = nullptr;
    static cudaEvent_t evF = nullptr, evJ = nullptr;
    if (s1 == nullptr) {
        cudaStreamCreateWithFlags(&s1, cudaStreamNonBlocking);
        cudaEventCreateWithFlags(&evF, cudaEventDisableTiming);
        cudaEventCreateWithFlags(&evJ, cudaEventDisableTiming);
    }

    const int smem = GEMM_SMEM;
    cudaFuncSetAttribute(gemm_fp16_half_kernel<float>,  cudaFuncAttributeMaxDynamicSharedMemorySize, smem);
    cudaFuncSetAttribute(gemm_fp16_half_kernel<__half>, cudaFuncAttributeMaxDynamicSharedMemorySize, smem);
    cudaFuncSetAttribute(gemm_fp16_head_kernel, cudaFuncAttributeMaxDynamicSharedMemorySize, smem);

    const int gemm_tiles = (Nn + TILE_M - 1) / TILE_M;        // 782
    const int gemm_grid2 = (gemm_tiles + 1) / 2;              // 391 (2-tile persistent)
    const int agg_grid  = Nn / 8;   // 6250, exact
    const int elem_grid = (Nn * 32 + 511) / 512;
    const int GL = NGg * Hh;
    const int WSZ = Hh * Hh;

    // ---- fork: preprocessing chain on s1, W1-convert + layer-1 GEMM on s0 ----
    cudaEventRecord(evF, 0);
    cudaStreamWaitEvent(s1, evF, 0);

    // s1: CSR construction (independent of GEMM path)
    hist_kernel<<<1024, 256, 0, s1>>>(ei, bt);
    scan_fused_kernel<<<NB_SCAN, 256, 0, s1>>>();
    scatter_kernel<<<(Ee + 255) / 256, 256, 0, s1>>>(ei);  // also zeroes gsum/gsq
    cudaEventRecord(evJ, s1);

    // s0 (default): W1 -> fp16, layer-1 GEMM, then remaining weights
    convert_w1_kernel<<<16, 256>>>(W1);
    gemm_fp16_half_kernel<float><<<gemm_grid2, 256, smem>>>(x, Wh + 0 * WSZ, Th, Nn);
    convert_wrest_kernel<<<64, 256>>>(Wm, WL, Wp1);  // done long before layer-2 GEMM

    // join before the first aggregation
    cudaStreamWaitEvent(0, evJ, 0);

    // ---- layer 1 aggregate + norm -> HBh ----
    agg_kernel<<<agg_grid, 256>>>(Th, b1, Ah, GS + 0 * GL, GQ + 0 * GL);
    final_kernel<0><<<elem_grid, 512>>>(Ah, nullptr, a1, g1, be1, HBh, GS + 0 * GL, GQ + 0 * GL);

    // ---- mid layer 0 (residual): HBh -> HAh ----
    gemm_fp16_half_kernel<__half><<<gemm_grid2, 256, smem>>>(HBh, Wh + 1 * WSZ, Th, Nn);
    agg_kernel<<<agg_grid, 256>>>(Th, bm + 0 * 128, Ah, GS + 1 * GL, GQ + 1 * GL);
    final_kernel<1><<<elem_grid, 512>>>(Ah, HBh, am + 0 * 128, gm + 0 * 128, bem + 0 * 128, HAh,
                                        GS + 1 * GL, GQ + 1 * GL);

    // ---- mid layer 1 (residual): HAh -> HBh ----
    gemm_fp16_half_kernel<__half><<<gemm_grid2, 256, smem>>>(HAh, Wh + 2 * WSZ, Th, Nn);
    agg_kernel<<<agg_grid, 256>>>(Th, bm + 1 * 128, Ah, GS + 2 * GL, GQ + 2 * GL);
    final_kernel<1><<<elem_grid, 512>>>(Ah, HAh, am + 1 * 128, gm + 1 * 128, bem + 1 * 128, HBh,
                                        GS + 2 * GL, GQ + 2 * GL);

    // ---- last layer: HBh -> HAh ----
    gemm_fp16_half_kernel<__half><<<gemm_grid2, 256, smem>>>(HBh, Wh + 3 * WSZ, Th, Nn);
    agg_kernel<<<agg_grid, 256>>>(Th, bL, Ah, GS + 3 * GL, GQ + 3 * GL);
    final_kernel<0><<<elem_grid, 512>>>(Ah, nullptr, aL, gL, beL, HAh, GS + 3 * GL, GQ + 3 * GL);

    // ---- predictor: HAh -> out (GEMM + fused head + safe cleanup) ----
    gemm_fp16_head_kernel<<<gemm_tiles, 256, smem>>>(HAh, Wh + 4 * WSZ, bp1, Wp2, bp2, out, Nn);
}